// round 7
// baseline (speedup 1.0000x reference)
#include <cuda_runtime.h>
#include <math.h>
#include <stdint.h>

#define NB   16
#define NN   512
#define DM   256
#define NH   8
#define HDIM 32
#define NL   3
#define NE   4096
#define IND  768
#define FFD  1024
#define ROWS (NB*NN)   // 8192

// ---------------- scratch (device globals; no allocation allowed) ----------
__device__ float g_bias[(size_t)NB*NH*NN*NN];   // 134 MB attn bias (B,H,N,N)
__device__ float g_x   [(size_t)ROWS*DM];
__device__ float g_qkv [(size_t)ROWS*3*DM];
__device__ float g_attn[(size_t)ROWS*DM];
__device__ float g_tmp [(size_t)ROWS*DM];
__device__ float g_ff  [(size_t)ROWS*FFD];

// ---------------- helpers --------------------------------------------------
__device__ __forceinline__ float geluf(float v) {
    return 0.5f * v * (1.0f + erff(v * 0.7071067811865476f));
}

__device__ __forceinline__ float blockReduceSum(float v, float* sh) {
    int lane = threadIdx.x & 31, w = threadIdx.x >> 5;
    #pragma unroll
    for (int o = 16; o > 0; o >>= 1) v += __shfl_down_sync(0xffffffffu, v, o);
    __syncthreads();
    if (lane == 0) sh[w] = v;
    __syncthreads();
    if (w == 0) {
        int nw = blockDim.x >> 5;
        float t = (lane < nw) ? sh[lane] : 0.0f;
        #pragma unroll
        for (int o = 16; o > 0; o >>= 1) t += __shfl_down_sync(0xffffffffu, t, o);
        if (lane == 0) sh[0] = t;
    }
    __syncthreads();
    return sh[0];
}

// ---------------- bias build ------------------------------------------------
__global__ void zero_kernel(float4* p, size_t n4) {
    size_t stride = (size_t)gridDim.x * blockDim.x;
    for (size_t i = (size_t)blockIdx.x * blockDim.x + threadIdx.x; i < n4; i += stride)
        p[i] = make_float4(0.f, 0.f, 0.f, 0.f);
}

__global__ void scatter_kernel(const int* __restrict__ edge_index,
                               const int* __restrict__ edge_type,
                               const float* __restrict__ edge_weight,
                               const float* __restrict__ et_emb,
                               float* __restrict__ bias) {
    int t = blockIdx.x * blockDim.x + threadIdx.x;
    if (t >= NB * NE) return;
    int b = t / NE, e = t % NE;
    int src = edge_index[(size_t)b * 2 * NE + e];
    int dst = edge_index[(size_t)b * 2 * NE + NE + e];
    int et  = edge_type[(size_t)b * NE + e];
    float w = edge_weight[(size_t)b * NE + e];
    float add = (et == 2) ? w : 0.0f;
    size_t base = (size_t)b * NH * NN * NN + (size_t)src * NN + dst;
    #pragma unroll
    for (int h = 0; h < NH; h++)
        atomicAdd(&bias[base + (size_t)h * NN * NN], et_emb[et * NH + h] + add);
}

// ---------------- tiled GEMM:  C = act(A[M,K] @ W[K,N] + b) ----------------
// BM=128, BN=64, BK=16, 256 threads, 8x4 outputs per thread, float4 I/O.
template <int ACT>
__global__ void gemm_kernel(const float* __restrict__ A, const float* __restrict__ W,
                            const float* __restrict__ bias, float* __restrict__ C,
                            int M, int K, int Nc) {
    __shared__ float As[128][17];   // padded: scalar broadcast reads
    __shared__ float Bs[16][64];    // unpadded: float4 reads
    int tx = threadIdx.x;
    int block_n = blockIdx.x * 64, block_m = blockIdx.y * 128;
    int trow = tx >> 4;             // 0..15 -> 8 rows each
    int tcol = tx & 15;             // 0..15 -> 4 cols each

    float acc[8][4];
    #pragma unroll
    for (int i = 0; i < 8; i++)
        #pragma unroll
        for (int j = 0; j < 4; j++) acc[i][j] = 0.f;

    for (int k0 = 0; k0 < K; k0 += 16) {
        // A tile: 128x16 = 512 float4, 2 per thread
        #pragma unroll
        for (int t = tx; t < 512; t += 256) {
            int mm = t >> 2;
            int kk = (t & 3) * 4;
            float4 v = *(const float4*)&A[(size_t)(block_m + mm) * K + k0 + kk];
            As[mm][kk] = v.x; As[mm][kk + 1] = v.y;
            As[mm][kk + 2] = v.z; As[mm][kk + 3] = v.w;
        }
        // B tile: 16x64 = 256 float4, 1 per thread
        {
            int kk = tx >> 4, nn = (tx & 15) * 4;
            float4 v = *(const float4*)&W[(size_t)(k0 + kk) * Nc + block_n + nn];
            *(float4*)&Bs[kk][nn] = v;
        }
        __syncthreads();
        #pragma unroll
        for (int kk = 0; kk < 16; kk++) {
            float a[8];
            #pragma unroll
            for (int i = 0; i < 8; i++) a[i] = As[trow * 8 + i][kk];
            float4 bv = *(const float4*)&Bs[kk][tcol * 4];
            float bb[4] = {bv.x, bv.y, bv.z, bv.w};
            #pragma unroll
            for (int i = 0; i < 8; i++)
                #pragma unroll
                for (int j = 0; j < 4; j++) acc[i][j] += a[i] * bb[j];
        }
        __syncthreads();
    }
    int nbase = block_n + tcol * 4;
    float4 bv = *(const float4*)&bias[nbase];
    float badd[4] = {bv.x, bv.y, bv.z, bv.w};
    #pragma unroll
    for (int i = 0; i < 8; i++) {
        float4 o;
        float v0 = acc[i][0] + badd[0];
        float v1 = acc[i][1] + badd[1];
        float v2 = acc[i][2] + badd[2];
        float v3 = acc[i][3] + badd[3];
        if (ACT == 1) { v0 = geluf(v0); v1 = geluf(v1); v2 = geluf(v2); v3 = geluf(v3); }
        o.x = v0; o.y = v1; o.z = v2; o.w = v3;
        *(float4*)&C[(size_t)(block_m + trow * 8 + i) * Nc + nbase] = o;
    }
}

// ---------------- attention (flash-style, fp32) ----------------------------
// One block per (b,h, 64-row i-tile). 256 threads: row r=tid>>2, q4=tid&3.
__global__ void attn_kernel(const float* __restrict__ qkv,
                            const float* __restrict__ bias,
                            const int* __restrict__ node_mask,
                            float* __restrict__ outp) {
    __shared__ float sQ[64][33];
    __shared__ float sK[32][33];
    __shared__ float sV[32][33];
    __shared__ float sP[64][33];

    int bh = blockIdx.y;            // 0..127
    int b = bh >> 3, h = bh & 7;
    int i0 = blockIdx.x * 64;
    int tid = threadIdx.x;
    int r = tid >> 2, q4 = tid & 3;
    const float scale = 0.17677669529663687f;   // 1/sqrt(32)

    for (int idx = tid; idx < 64 * 32; idx += 256) {
        int i = idx >> 5, d = idx & 31;
        sQ[i][d] = qkv[((size_t)(b * NN + i0 + i)) * (3 * DM) + h * HDIM + d];
    }
    __syncthreads();

    float qreg[32];
    #pragma unroll
    for (int d = 0; d < 32; d++) qreg[d] = sQ[r][d];

    float m = -INFINITY, l = 0.f;
    float o[8];
    #pragma unroll
    for (int dd = 0; dd < 8; dd++) o[dd] = 0.f;

    const float* biasrow = bias + ((size_t)bh * NN + (i0 + r)) * NN;

    for (int j0 = 0; j0 < NN; j0 += 32) {
        for (int idx = tid; idx < 32 * 32; idx += 256) {
            int j = idx >> 5, d = idx & 31;
            size_t base = ((size_t)(b * NN + j0 + j)) * (3 * DM) + h * HDIM + d;
            sK[j][d] = qkv[base + DM];
            sV[j][d] = qkv[base + 2 * DM];
        }
        __syncthreads();

        float sreg[8];
        #pragma unroll
        for (int jj = 0; jj < 8; jj++) {
            int j = q4 * 8 + jj;
            float s = 0.f;
            #pragma unroll
            for (int d = 0; d < 32; d++) s += qreg[d] * sK[j][d];
            s = s * scale + biasrow[j0 + j];
            if (node_mask[b * NN + j0 + j] == 0) s = -INFINITY;
            sreg[jj] = s;
        }
        float mx = sreg[0];
        #pragma unroll
        for (int jj = 1; jj < 8; jj++) mx = fmaxf(mx, sreg[jj]);
        mx = fmaxf(mx, __shfl_xor_sync(0xffffffffu, mx, 1));
        mx = fmaxf(mx, __shfl_xor_sync(0xffffffffu, mx, 2));

        float mnew = fmaxf(m, mx);
        float corr = (mnew == -INFINITY) ? 1.f : __expf(m - mnew);

        float ls = 0.f;
        #pragma unroll
        for (int jj = 0; jj < 8; jj++) {
            float p = (sreg[jj] == -INFINITY) ? 0.f : __expf(sreg[jj] - mnew);
            sP[r][q4 * 8 + jj] = p;
            ls += p;
        }
        ls += __shfl_xor_sync(0xffffffffu, ls, 1);
        ls += __shfl_xor_sync(0xffffffffu, ls, 2);
        l = l * corr + ls;
        #pragma unroll
        for (int dd = 0; dd < 8; dd++) o[dd] *= corr;
        __syncwarp();

        #pragma unroll
        for (int dd = 0; dd < 8; dd++) {
            int d = q4 * 8 + dd;
            float acc = 0.f;
            #pragma unroll
            for (int j = 0; j < 32; j++) acc += sP[r][j] * sV[j][d];
            o[dd] += acc;
        }
        m = mnew;
        __syncthreads();
    }

    float inv = (l > 0.f) ? 1.f / l : 0.f;
    #pragma unroll
    for (int dd = 0; dd < 8; dd++)
        outp[((size_t)(b * NN + i0 + r)) * DM + h * HDIM + q4 * 8 + dd] = o[dd] * inv;
}

// ---------------- residual + LayerNorm -------------------------------------
__global__ void add_ln_kernel(const float* __restrict__ xin, const float* __restrict__ res,
                              const float* __restrict__ g, const float* __restrict__ bb,
                              float* __restrict__ xout) {
    __shared__ float red[32];
    int row = blockIdx.x, tid = threadIdx.x;
    float v = xin[(size_t)row * DM + tid] + res[(size_t)row * DM + tid];
    float mu = blockReduceSum(v, red) * (1.0f / DM);
    float c = v - mu;
    float var = blockReduceSum(c * c, red) * (1.0f / DM);
    xout[(size_t)row * DM + tid] = c * rsqrtf(var + 1e-5f) * g[tid] + bb[tid];
}

// ---------------- pooling + MLP head ---------------------------------------
__global__ void head_kernel(const float* __restrict__ x,
                            const int* __restrict__ tmask, const int* __restrict__ imask,
                            const int* __restrict__ gidx,
                            const float* __restrict__ Wm1, const float* __restrict__ bm1,
                            const float* __restrict__ Wm2, const float* __restrict__ bm2,
                            const float* __restrict__ Wm3, const float* __restrict__ bm3,
                            float* __restrict__ out) {
    __shared__ float red[32];
    __shared__ float comb[769];
    __shared__ float h1[512];
    __shared__ float h2[256];
    int b = blockIdx.x, tid = threadIdx.x;

    float tcp = 0.f, icp = 0.f;
    for (int n = tid; n < NN; n += 256) {
        tcp += (tmask[b * NN + n] != 0) ? 1.f : 0.f;
        icp += (imask[b * NN + n] != 0) ? 1.f : 0.f;
    }
    float tc = fmaxf(blockReduceSum(tcp, red), 1.f);
    float ic = fmaxf(blockReduceSum(icp, red), 1.f);

    int d = tid;
    float tp = 0.f, ip = 0.f;
    for (int n = 0; n < NN; n++) {
        float v = x[((size_t)(b * NN + n)) * DM + d];
        if (tmask[b * NN + n] != 0) tp += v;
        if (imask[b * NN + n] != 0) ip += v;
    }
    tp /= tc; ip /= ic;
    int gi = gidx[b];
    float ge = x[((size_t)(b * NN + gi)) * DM + d];

    float n1s = blockReduceSum(tp * tp, red);
    float n2s = blockReduceSum(ip * ip, red);
    float dt  = blockReduceSum(tp * ip, red);
    float n1 = fmaxf(sqrtf(n1s), 1e-6f), n2 = fmaxf(sqrtf(n2s), 1e-6f);
    float conflict = 1.f - dt / (n1 * n2);

    comb[d] = ge; comb[256 + d] = tp; comb[512 + d] = ip;
    if (tid == 0) comb[768] = conflict;
    __syncthreads();

    for (int j = tid; j < 512; j += 256) {
        float a = bm1[j];
        for (int i = 0; i < 769; i++) a += comb[i] * Wm1[(size_t)i * 512 + j];
        h1[j] = geluf(a);
    }
    __syncthreads();
    {
        float a = bm2[tid];
        for (int i = 0; i < 512; i++) a += h1[i] * Wm2[(size_t)i * 256 + tid];
        h2[tid] = geluf(a);
    }
    __syncthreads();
    float tot = blockReduceSum(h2[tid] * Wm3[tid], red);
    if (tid == 0) out[b] = tot + bm3[0];
}

// ---------------- launch ----------------------------------------------------
extern "C" void kernel_launch(void* const* d_in, const int* in_sizes, int n_in,
                              void* d_out, int out_size) {
    const float* node_feats = (const float*)d_in[0];
    const int*   node_mask  = (const int*)d_in[1];
    const int*   text_mask  = (const int*)d_in[2];
    const int*   image_mask = (const int*)d_in[3];
    const int*   gidx       = (const int*)d_in[4];
    const int*   edge_index = (const int*)d_in[5];
    const int*   edge_type  = (const int*)d_in[6];
    const float* edge_weight= (const float*)d_in[7];
    const float* W_in  = (const float*)d_in[8];
    const float* b_in  = (const float*)d_in[9];
    const float* Wqkv  = (const float*)d_in[10];
    const float* bqkv  = (const float*)d_in[11];
    const float* Wo    = (const float*)d_in[12];
    const float* bo    = (const float*)d_in[13];
    const float* ln1_g = (const float*)d_in[14];
    const float* ln1_b = (const float*)d_in[15];
    const float* ln2_g = (const float*)d_in[16];
    const float* ln2_b = (const float*)d_in[17];
    const float* Wff1  = (const float*)d_in[18];
    const float* bff1  = (const float*)d_in[19];
    const float* Wff2  = (const float*)d_in[20];
    const float* bff2  = (const float*)d_in[21];
    const float* et_emb= (const float*)d_in[22];
    const float* Wm1   = (const float*)d_in[23];
    const float* bm1   = (const float*)d_in[24];
    const float* Wm2   = (const float*)d_in[25];
    const float* bm2   = (const float*)d_in[26];
    const float* Wm3   = (const float*)d_in[27];
    const float* bm3   = (const float*)d_in[28];

    float *bias, *x, *qkv, *attn, *tmp, *ff;
    cudaGetSymbolAddress((void**)&bias, g_bias);
    cudaGetSymbolAddress((void**)&x,    g_x);
    cudaGetSymbolAddress((void**)&qkv,  g_qkv);
    cudaGetSymbolAddress((void**)&attn, g_attn);
    cudaGetSymbolAddress((void**)&tmp,  g_tmp);
    cudaGetSymbolAddress((void**)&ff,   g_ff);

    size_t bias_elems = (size_t)NB * NH * NN * NN;
    zero_kernel<<<4096, 256>>>((float4*)bias, bias_elems / 4);
    scatter_kernel<<<(NB * NE + 255) / 256, 256>>>(edge_index, edge_type, edge_weight, et_emb, bias);

    // input projection
    gemm_kernel<0><<<dim3(DM / 64, ROWS / 128), 256>>>(node_feats, W_in, b_in, x, ROWS, IND, DM);

    for (int l = 0; l < NL; l++) {
        gemm_kernel<0><<<dim3(3 * DM / 64, ROWS / 128), 256>>>(
            x, Wqkv + (size_t)l * DM * 3 * DM, bqkv + (size_t)l * 3 * DM, qkv, ROWS, DM, 3 * DM);
        attn_kernel<<<dim3(NN / 64, NB * NH), 256>>>(qkv, bias, node_mask, attn);
        gemm_kernel<0><<<dim3(DM / 64, ROWS / 128), 256>>>(
            attn, Wo + (size_t)l * DM * DM, bo + (size_t)l * DM, tmp, ROWS, DM, DM);
        add_ln_kernel<<<ROWS, 256>>>(x, tmp, ln1_g + (size_t)l * DM, ln1_b + (size_t)l * DM, x);
        gemm_kernel<1><<<dim3(FFD / 64, ROWS / 128), 256>>>(
            x, Wff1 + (size_t)l * DM * FFD, bff1 + (size_t)l * FFD, ff, ROWS, DM, FFD);
        gemm_kernel<0><<<dim3(DM / 64, ROWS / 128), 256>>>(
            ff, Wff2 + (size_t)l * FFD * DM, bff2 + (size_t)l * DM, tmp, ROWS, FFD, DM);
        add_ln_kernel<<<ROWS, 256>>>(x, tmp, ln2_g + (size_t)l * DM, ln2_b + (size_t)l * DM, x);
    }

    head_kernel<<<NB, 256>>>(x, text_mask, image_mask, gidx,
                             Wm1, bm1, Wm2, bm2, Wm3, bm3, (float*)d_out);
}

// round 11
// speedup vs baseline: 1.1823x; 1.1823x over previous
#include <cuda_runtime.h>
#include <cuda_bf16.h>
#include <math.h>
#include <stdint.h>

#define NB   16
#define NN   512
#define DM   256
#define NH   8
#define HDIM 32
#define NL   3
#define NE   4096
#define IND  768
#define FFD  1024
#define ROWS (NB*NN)   // 8192

// ---------------- scratch (device globals; no allocation allowed) ----------
__device__ float g_bias[(size_t)NB*NH*NN*NN];   // 134 MB attn bias (B,H,N,N)
__device__ float g_x   [(size_t)ROWS*DM];
__device__ float g_qkv [(size_t)ROWS*3*DM];
__device__ float g_attn[(size_t)ROWS*DM];
__device__ float g_tmp [(size_t)ROWS*DM];
__device__ float g_ff  [(size_t)ROWS*FFD];
// transposed + split weights, [N][K] layout, bf16 hi/lo
#define WT_IN_OFF   0
#define WT_LAYER(l) (196608 + (size_t)(l) * 786432)
#define WT_QKV_OFF  0
#define WT_WO_OFF   196608
#define WT_FF1_OFF  (196608 + 65536)
#define WT_FF2_OFF  (196608 + 65536 + 262144)
__device__ __nv_bfloat16 g_wt_hi[2555904];
__device__ __nv_bfloat16 g_wt_lo[2555904];

// ---------------- helpers --------------------------------------------------
__device__ __forceinline__ uint32_t smem_u32(const void* p) {
    uint32_t a;
    asm("{ .reg .u64 t; cvta.to.shared.u64 t, %1; cvt.u32.u64 %0, t; }" : "=r"(a) : "l"(p));
    return a;
}
__device__ __forceinline__ float geluf(float v) {
    return 0.5f * v * (1.0f + erff(v * 0.7071067811865476f));
}
__device__ __forceinline__ float blockReduceSum(float v, float* sh) {
    int lane = threadIdx.x & 31, w = threadIdx.x >> 5;
    #pragma unroll
    for (int o = 16; o > 0; o >>= 1) v += __shfl_down_sync(0xffffffffu, v, o);
    __syncthreads();
    if (lane == 0) sh[w] = v;
    __syncthreads();
    if (w == 0) {
        int nw = blockDim.x >> 5;
        float t = (lane < nw) ? sh[lane] : 0.0f;
        #pragma unroll
        for (int o = 16; o > 0; o >>= 1) t += __shfl_down_sync(0xffffffffu, t, o);
        if (lane == 0) sh[0] = t;
    }
    __syncthreads();
    return sh[0];
}

#define LDMATRIX_X4(r0, r1, r2, r3, a) \
    asm volatile("ldmatrix.sync.aligned.m8n8.x4.shared.b16 {%0,%1,%2,%3}, [%4];" \
                 : "=r"(r0), "=r"(r1), "=r"(r2), "=r"(r3) : "r"(a))
#define LDMATRIX_X2(r0, r1, a) \
    asm volatile("ldmatrix.sync.aligned.m8n8.x2.shared.b16 {%0,%1}, [%2];" \
                 : "=r"(r0), "=r"(r1) : "r"(a))
#define MMA_BF16(c, a, b) \
    asm volatile("mma.sync.aligned.m16n8k16.row.col.f32.bf16.bf16.f32 " \
                 "{%0,%1,%2,%3}, {%4,%5,%6,%7}, {%8,%9}, {%0,%1,%2,%3};" \
                 : "+f"((c)[0]), "+f"((c)[1]), "+f"((c)[2]), "+f"((c)[3]) \
                 : "r"((a)[0]), "r"((a)[1]), "r"((a)[2]), "r"((a)[3]), \
                   "r"((b)[0]), "r"((b)[1]))

// ---------------- bias build ------------------------------------------------
__global__ void zero_kernel(float4* p, size_t n4) {
    size_t stride = (size_t)gridDim.x * blockDim.x;
    for (size_t i = (size_t)blockIdx.x * blockDim.x + threadIdx.x; i < n4; i += stride)
        p[i] = make_float4(0.f, 0.f, 0.f, 0.f);
}
__global__ void scatter_kernel(const int* __restrict__ edge_index,
                               const int* __restrict__ edge_type,
                               const float* __restrict__ edge_weight,
                               const float* __restrict__ et_emb,
                               float* __restrict__ bias) {
    int t = blockIdx.x * blockDim.x + threadIdx.x;
    if (t >= NB * NE) return;
    int b = t / NE, e = t % NE;
    int src = edge_index[(size_t)b * 2 * NE + e];
    int dst = edge_index[(size_t)b * 2 * NE + NE + e];
    int et  = edge_type[(size_t)b * NE + e];
    float w = edge_weight[(size_t)b * NE + e];
    float add = (et == 2) ? w : 0.0f;
    size_t base = (size_t)b * NH * NN * NN + (size_t)src * NN + dst;
    #pragma unroll
    for (int h = 0; h < NH; h++)
        atomicAdd(&bias[base + (size_t)h * NN * NN], et_emb[et * NH + h] + add);
}

// --------- weight transpose + bf16 split: out[n][k] = split(W[k][n]) --------
__global__ void split_kernel(const float* __restrict__ W,
                             __nv_bfloat16* __restrict__ hi, __nv_bfloat16* __restrict__ lo,
                             int K, int Nc) {
    __shared__ float t[32][33];
    int n0 = blockIdx.x * 32, k0 = blockIdx.y * 32;
    int x = threadIdx.x, y = threadIdx.y;   // 32 x 8
    #pragma unroll
    for (int i = y; i < 32; i += 8) t[i][x] = W[(size_t)(k0 + i) * Nc + n0 + x];
    __syncthreads();
    #pragma unroll
    for (int i = y; i < 32; i += 8) {
        float v = t[x][i];
        __nv_bfloat16 h = __float2bfloat16_rn(v);
        float l = v - __bfloat162float(h);
        size_t o = (size_t)(n0 + i) * K + k0 + x;
        hi[o] = h;
        lo[o] = __float2bfloat16_rn(l);
    }
}

// ---------------- split-bf16 mma.sync GEMM ----------------------------------
// C[M,Nc] = act(A[M,K] @ Wt[Nc,K]^T + bias), fp32-accurate via hi/lo split.
// Block tile 128x64, K-chunk 32, 256 threads (8 warps), warp tile 32x32.
#define ASTR 40   // bf16 row stride in smem (80B, conflict-free for ldmatrix)
template <int ACT>
__global__ void mma_gemm_kernel(const float* __restrict__ A,
                                const __nv_bfloat16* __restrict__ Whi,
                                const __nv_bfloat16* __restrict__ Wlo,
                                const float* __restrict__ bias, float* __restrict__ C,
                                int K, int Nc) {
    __shared__ __nv_bfloat16 sAh[128 * ASTR], sAl[128 * ASTR];
    __shared__ __nv_bfloat16 sBh[64 * ASTR],  sBl[64 * ASTR];
    int tid = threadIdx.x;
    int warp = tid >> 5, lane = tid & 31;
    int wm = warp & 3, wn = warp >> 2;          // warp tile (wm*32, wn*32)
    int bm = blockIdx.y * 128, bn = blockIdx.x * 64;

    float acc[2][4][4];
    #pragma unroll
    for (int i = 0; i < 2; i++)
        #pragma unroll
        for (int j = 0; j < 4; j++)
            #pragma unroll
            for (int q = 0; q < 4; q++) acc[i][j][q] = 0.f;

    // fill pointers
    int arow = tid >> 1, ahalf = tid & 1;
    const float* ap = A + (size_t)(bm + arow) * K + ahalf * 16;
    int brow = tid >> 2, bseg = tid & 3;
    const __nv_bfloat16* bph = Whi + (size_t)(bn + brow) * K + bseg * 8;
    const __nv_bfloat16* bpl = Wlo + (size_t)(bn + brow) * K + bseg * 8;

    uint32_t uAh = smem_u32(sAh), uAl = smem_u32(sAl);
    uint32_t uBh = smem_u32(sBh), uBl = smem_u32(sBl);

    // ldmatrix per-lane address components (element offsets within tile)
    int a_r = (lane & 7) + ((lane >> 3) & 1) * 8;   // row within 16
    int a_c = (lane >> 4) * 8;                      // k-col within 16
    int ll = lane & 15;
    int b_r = ll & 7;                               // row within 8
    int b_c = (ll >> 3) * 8;                        // k-col within 16

    for (int k0 = 0; k0 < K; k0 += 32) {
        // ---- fill A (split on the fly): 128 rows x 32 floats ----
        #pragma unroll
        for (int j = 0; j < 4; j++) {
            float4 v = *(const float4*)(ap + k0 + j * 4);
            __nv_bfloat162 h0 = __floats2bfloat162_rn(v.x, v.y);
            __nv_bfloat162 h1 = __floats2bfloat162_rn(v.z, v.w);
            __nv_bfloat162 l0 = __floats2bfloat162_rn(v.x - __low2float(h0), v.y - __high2float(h0));
            __nv_bfloat162 l1 = __floats2bfloat162_rn(v.z - __low2float(h1), v.w - __high2float(h1));
            int e = arow * ASTR + ahalf * 16 + j * 4;
            *(__nv_bfloat162*)(sAh + e) = h0; *(__nv_bfloat162*)(sAh + e + 2) = h1;
            *(__nv_bfloat162*)(sAl + e) = l0; *(__nv_bfloat162*)(sAl + e + 2) = l1;
        }
        // ---- fill B: 64 rows x 32 bf16 (pre-split) ----
        {
            int e = brow * ASTR + bseg * 8;
            *(uint4*)(sBh + e) = *(const uint4*)(bph + k0);
            *(uint4*)(sBl + e) = *(const uint4*)(bpl + k0);
        }
        __syncthreads();

        #pragma unroll
        for (int s = 0; s < 32; s += 16) {
            uint32_t ah[2][4], al[2][4], bh[4][2], bl[4][2];
            #pragma unroll
            for (int mi = 0; mi < 2; mi++) {
                int off = ((wm * 32 + mi * 16 + a_r) * ASTR + s + a_c) * 2;
                LDMATRIX_X4(ah[mi][0], ah[mi][1], ah[mi][2], ah[mi][3], uAh + off);
                LDMATRIX_X4(al[mi][0], al[mi][1], al[mi][2], al[mi][3], uAl + off);
            }
            #pragma unroll
            for (int ni = 0; ni < 4; ni++) {
                int off = ((wn * 32 + ni * 8 + b_r) * ASTR + s + b_c) * 2;
                LDMATRIX_X2(bh[ni][0], bh[ni][1], uBh + off);
                LDMATRIX_X2(bl[ni][0], bl[ni][1], uBl + off);
            }
            #pragma unroll
            for (int mi = 0; mi < 2; mi++)
                #pragma unroll
                for (int ni = 0; ni < 4; ni++) {
                    MMA_BF16(acc[mi][ni], ah[mi], bh[ni]);
                    MMA_BF16(acc[mi][ni], ah[mi], bl[ni]);
                    MMA_BF16(acc[mi][ni], al[mi], bh[ni]);
                }
        }
        __syncthreads();
    }

    // ---- epilogue ----
    int gid = lane >> 2, tid2 = (lane & 3) * 2;
    #pragma unroll
    for (int mi = 0; mi < 2; mi++) {
        #pragma unroll
        for (int ni = 0; ni < 4; ni++) {
            int row = bm + wm * 32 + mi * 16 + gid;
            int col = bn + wn * 32 + ni * 8 + tid2;
            float b0 = bias[col], b1 = bias[col + 1];
            float v0 = acc[mi][ni][0] + b0, v1 = acc[mi][ni][1] + b1;
            float v2 = acc[mi][ni][2] + b0, v3 = acc[mi][ni][3] + b1;
            if (ACT == 1) { v0 = geluf(v0); v1 = geluf(v1); v2 = geluf(v2); v3 = geluf(v3); }
            *(float2*)&C[(size_t)row * Nc + col] = make_float2(v0, v1);
            *(float2*)&C[(size_t)(row + 8) * Nc + col] = make_float2(v2, v3);
        }
    }
}

// ---------------- attention (flash-style, fp32) ----------------------------
__global__ void attn_kernel(const float* __restrict__ qkv,
                            const float* __restrict__ bias,
                            const int* __restrict__ node_mask,
                            float* __restrict__ outp) {
    __shared__ float sQ[64][33];
    __shared__ float sK[32][33];
    __shared__ float sV[32][33];
    __shared__ float sP[64][33];

    int bh = blockIdx.y;
    int b = bh >> 3, h = bh & 7;
    int i0 = blockIdx.x * 64;
    int tid = threadIdx.x;
    int r = tid >> 2, q4 = tid & 3;
    const float scale = 0.17677669529663687f;

    for (int idx = tid; idx < 64 * 32; idx += 256) {
        int i = idx >> 5, d = idx & 31;
        sQ[i][d] = qkv[((size_t)(b * NN + i0 + i)) * (3 * DM) + h * HDIM + d];
    }
    __syncthreads();

    float qreg[32];
    #pragma unroll
    for (int d = 0; d < 32; d++) qreg[d] = sQ[r][d];

    float m = -INFINITY, l = 0.f;
    float o[8];
    #pragma unroll
    for (int dd = 0; dd < 8; dd++) o[dd] = 0.f;

    const float* biasrow = bias + ((size_t)bh * NN + (i0 + r)) * NN;

    for (int j0 = 0; j0 < NN; j0 += 32) {
        for (int idx = tid; idx < 32 * 32; idx += 256) {
            int j = idx >> 5, d = idx & 31;
            size_t base = ((size_t)(b * NN + j0 + j)) * (3 * DM) + h * HDIM + d;
            sK[j][d] = qkv[base + DM];
            sV[j][d] = qkv[base + 2 * DM];
        }
        __syncthreads();

        float sreg[8];
        #pragma unroll
        for (int jj = 0; jj < 8; jj++) {
            int j = q4 * 8 + jj;
            float s = 0.f;
            #pragma unroll
            for (int d = 0; d < 32; d++) s += qreg[d] * sK[j][d];
            s = s * scale + biasrow[j0 + j];
            if (node_mask[b * NN + j0 + j] == 0) s = -INFINITY;
            sreg[jj] = s;
        }
        float mx = sreg[0];
        #pragma unroll
        for (int jj = 1; jj < 8; jj++) mx = fmaxf(mx, sreg[jj]);
        mx = fmaxf(mx, __shfl_xor_sync(0xffffffffu, mx, 1));
        mx = fmaxf(mx, __shfl_xor_sync(0xffffffffu, mx, 2));

        float mnew = fmaxf(m, mx);
        float corr = (mnew == -INFINITY) ? 1.f : __expf(m - mnew);

        float ls = 0.f;
        #pragma unroll
        for (int jj = 0; jj < 8; jj++) {
            float p = (sreg[jj] == -INFINITY) ? 0.f : __expf(sreg[jj] - mnew);
            sP[r][q4 * 8 + jj] = p;
            ls += p;
        }
        ls += __shfl_xor_sync(0xffffffffu, ls, 1);
        ls += __shfl_xor_sync(0xffffffffu, ls, 2);
        l = l * corr + ls;
        #pragma unroll
        for (int dd = 0; dd < 8; dd++) o[dd] *= corr;
        __syncwarp();

        #pragma unroll
        for (int dd = 0; dd < 8; dd++) {
            int d = q4 * 8 + dd;
            float acc = 0.f;
            #pragma unroll
            for (int j = 0; j < 32; j++) acc += sP[r][j] * sV[j][d];
            o[dd] += acc;
        }
        m = mnew;
        __syncthreads();
    }

    float inv = (l > 0.f) ? 1.f / l : 0.f;
    #pragma unroll
    for (int dd = 0; dd < 8; dd++)
        outp[((size_t)(b * NN + i0 + r)) * DM + h * HDIM + q4 * 8 + dd] = o[dd] * inv;
}

// ---------------- residual + LayerNorm -------------------------------------
__global__ void add_ln_kernel(const float* __restrict__ xin, const float* __restrict__ res,
                              const float* __restrict__ g, const float* __restrict__ bb,
                              float* __restrict__ xout) {
    __shared__ float red[32];
    int row = blockIdx.x, tid = threadIdx.x;
    float v = xin[(size_t)row * DM + tid] + res[(size_t)row * DM + tid];
    float mu = blockReduceSum(v, red) * (1.0f / DM);
    float c = v - mu;
    float var = blockReduceSum(c * c, red) * (1.0f / DM);
    xout[(size_t)row * DM + tid] = c * rsqrtf(var + 1e-5f) * g[tid] + bb[tid];
}

// ---------------- pooling + MLP head ---------------------------------------
__global__ void head_kernel(const float* __restrict__ x,
                            const int* __restrict__ tmask, const int* __restrict__ imask,
                            const int* __restrict__ gidx,
                            const float* __restrict__ Wm1, const float* __restrict__ bm1,
                            const float* __restrict__ Wm2, const float* __restrict__ bm2,
                            const float* __restrict__ Wm3, const float* __restrict__ bm3,
                            float* __restrict__ out) {
    __shared__ float red[32];
    __shared__ float comb[769];
    __shared__ float h1[512];
    __shared__ float h2[256];
    int b = blockIdx.x, tid = threadIdx.x;

    float tcp = 0.f, icp = 0.f;
    for (int n = tid; n < NN; n += 256) {
        tcp += (tmask[b * NN + n] != 0) ? 1.f : 0.f;
        icp += (imask[b * NN + n] != 0) ? 1.f : 0.f;
    }
    float tc = fmaxf(blockReduceSum(tcp, red), 1.f);
    float ic = fmaxf(blockReduceSum(icp, red), 1.f);

    int d = tid;
    float tp = 0.f, ip = 0.f;
    for (int n = 0; n < NN; n++) {
        float v = x[((size_t)(b * NN + n)) * DM + d];
        if (tmask[b * NN + n] != 0) tp += v;
        if (imask[b * NN + n] != 0) ip += v;
    }
    tp /= tc; ip /= ic;
    int gi = gidx[b];
    float ge = x[((size_t)(b * NN + gi)) * DM + d];

    float n1s = blockReduceSum(tp * tp, red);
    float n2s = blockReduceSum(ip * ip, red);
    float dt  = blockReduceSum(tp * ip, red);
    float n1 = fmaxf(sqrtf(n1s), 1e-6f), n2 = fmaxf(sqrtf(n2s), 1e-6f);
    float conflict = 1.f - dt / (n1 * n2);

    comb[d] = ge; comb[256 + d] = tp; comb[512 + d] = ip;
    if (tid == 0) comb[768] = conflict;
    __syncthreads();

    for (int j = tid; j < 512; j += 256) {
        float a = bm1[j];
        for (int i = 0; i < 769; i++) a += comb[i] * Wm1[(size_t)i * 512 + j];
        h1[j] = geluf(a);
    }
    __syncthreads();
    {
        float a = bm2[tid];
        for (int i = 0; i < 512; i++) a += h1[i] * Wm2[(size_t)i * 256 + tid];
        h2[tid] = geluf(a);
    }
    __syncthreads();
    float tot = blockReduceSum(h2[tid] * Wm3[tid], red);
    if (tid == 0) out[b] = tot + bm3[0];
}

// ---------------- launch ----------------------------------------------------
extern "C" void kernel_launch(void* const* d_in, const int* in_sizes, int n_in,
                              void* d_out, int out_size) {
    const float* node_feats = (const float*)d_in[0];
    const int*   node_mask  = (const int*)d_in[1];
    const int*   text_mask  = (const int*)d_in[2];
    const int*   image_mask = (const int*)d_in[3];
    const int*   gidx       = (const int*)d_in[4];
    const int*   edge_index = (const int*)d_in[5];
    const int*   edge_type  = (const int*)d_in[6];
    const float* edge_weight= (const float*)d_in[7];
    const float* W_in  = (const float*)d_in[8];
    const float* b_in  = (const float*)d_in[9];
    const float* Wqkv  = (const float*)d_in[10];
    const float* bqkv  = (const float*)d_in[11];
    const float* Wo    = (const float*)d_in[12];
    const float* bo    = (const float*)d_in[13];
    const float* ln1_g = (const float*)d_in[14];
    const float* ln1_b = (const float*)d_in[15];
    const float* ln2_g = (const float*)d_in[16];
    const float* ln2_b = (const float*)d_in[17];
    const float* Wff1  = (const float*)d_in[18];
    const float* bff1  = (const float*)d_in[19];
    const float* Wff2  = (const float*)d_in[20];
    const float* bff2  = (const float*)d_in[21];
    const float* et_emb= (const float*)d_in[22];
    const float* Wm1   = (const float*)d_in[23];
    const float* bm1   = (const float*)d_in[24];
    const float* Wm2   = (const float*)d_in[25];
    const float* bm2   = (const float*)d_in[26];
    const float* Wm3   = (const float*)d_in[27];
    const float* bm3   = (const float*)d_in[28];

    float *bias, *x, *qkv, *attn, *tmp, *ff;
    __nv_bfloat16 *wth, *wtl;
    cudaGetSymbolAddress((void**)&bias, g_bias);
    cudaGetSymbolAddress((void**)&x,    g_x);
    cudaGetSymbolAddress((void**)&qkv,  g_qkv);
    cudaGetSymbolAddress((void**)&attn, g_attn);
    cudaGetSymbolAddress((void**)&tmp,  g_tmp);
    cudaGetSymbolAddress((void**)&ff,   g_ff);
    cudaGetSymbolAddress((void**)&wth,  g_wt_hi);
    cudaGetSymbolAddress((void**)&wtl,  g_wt_lo);

    // ---- weight transpose + split (W[K,N] -> hi/lo[N,K]) ----
    split_kernel<<<dim3(DM / 32, IND / 32), dim3(32, 8)>>>(W_in, wth + WT_IN_OFF, wtl + WT_IN_OFF, IND, DM);
    for (int l = 0; l < NL; l++) {
        size_t lo = WT_LAYER(l);
        split_kernel<<<dim3(3 * DM / 32, DM / 32), dim3(32, 8)>>>(
            Wqkv + (size_t)l * DM * 3 * DM, wth + lo + WT_QKV_OFF, wtl + lo + WT_QKV_OFF, DM, 3 * DM);
        split_kernel<<<dim3(DM / 32, DM / 32), dim3(32, 8)>>>(
            Wo + (size_t)l * DM * DM, wth + lo + WT_WO_OFF, wtl + lo + WT_WO_OFF, DM, DM);
        split_kernel<<<dim3(FFD / 32, DM / 32), dim3(32, 8)>>>(
            Wff1 + (size_t)l * DM * FFD, wth + lo + WT_FF1_OFF, wtl + lo + WT_FF1_OFF, DM, FFD);
        split_kernel<<<dim3(DM / 32, FFD / 32), dim3(32, 8)>>>(
            Wff2 + (size_t)l * FFD * DM, wth + lo + WT_FF2_OFF, wtl + lo + WT_FF2_OFF, FFD, DM);
    }

    size_t bias_elems = (size_t)NB * NH * NN * NN;
    zero_kernel<<<4096, 256>>>((float4*)bias, bias_elems / 4);
    scatter_kernel<<<(NB * NE + 255) / 256, 256>>>(edge_index, edge_type, edge_weight, et_emb, bias);

    // input projection
    mma_gemm_kernel<0><<<dim3(DM / 64, ROWS / 128), 256>>>(
        node_feats, wth + WT_IN_OFF, wtl + WT_IN_OFF, b_in, x, IND, DM);

    for (int l = 0; l < NL; l++) {
        size_t lo = WT_LAYER(l);
        mma_gemm_kernel<0><<<dim3(3 * DM / 64, ROWS / 128), 256>>>(
            x, wth + lo + WT_QKV_OFF, wtl + lo + WT_QKV_OFF, bqkv + (size_t)l * 3 * DM, qkv, DM, 3 * DM);
        attn_kernel<<<dim3(NN / 64, NB * NH), 256>>>(qkv, bias, node_mask, attn);
        mma_gemm_kernel<0><<<dim3(DM / 64, ROWS / 128), 256>>>(
            attn, wth + lo + WT_WO_OFF, wtl + lo + WT_WO_OFF, bo + (size_t)l * DM, tmp, DM, DM);
        add_ln_kernel<<<ROWS, 256>>>(x, tmp, ln1_g + (size_t)l * DM, ln1_b + (size_t)l * DM, x);
        mma_gemm_kernel<1><<<dim3(FFD / 64, ROWS / 128), 256>>>(
            x, wth + lo + WT_FF1_OFF, wtl + lo + WT_FF1_OFF, bff1 + (size_t)l * FFD, ff, DM, FFD);
        mma_gemm_kernel<0><<<dim3(DM / 64, ROWS / 128), 256>>>(
            ff, wth + lo + WT_FF2_OFF, wtl + lo + WT_FF2_OFF, bff2 + (size_t)l * DM, tmp, FFD, DM);
        add_ln_kernel<<<ROWS, 256>>>(x, tmp, ln2_g + (size_t)l * DM, ln2_b + (size_t)l * DM, x);
    }

    head_kernel<<<NB, 256>>>(x, text_mask, image_mask, gidx,
                             Wm1, bm1, Wm2, bm2, Wm3, bm3, (float*)d_out);
}

// round 13
// speedup vs baseline: 2.7276x; 2.3070x over previous
#include <cuda_runtime.h>
#include <cuda_bf16.h>
#include <math.h>
#include <stdint.h>

#define NB   16
#define NN   512
#define DM   256
#define NH   8
#define HDIM 32
#define NL   3
#define NE   4096
#define IND  768
#define FFD  1024
#define ROWS (NB*NN)   // 8192

// ---------------- scratch (device globals; no allocation allowed) ----------
__device__ float g_bias[(size_t)NB*NH*NN*NN];   // 134 MB attn bias (B,H,N,N)
__device__ float g_x   [(size_t)ROWS*DM];
__device__ float g_qkv [(size_t)ROWS*3*DM];
__device__ float g_attn[(size_t)ROWS*DM];
__device__ float g_tmp [(size_t)ROWS*DM];
__device__ float g_ff  [(size_t)ROWS*FFD];
// transposed + split weights, [N][K] layout, bf16 hi/lo
#define WT_IN_OFF   0
#define WT_LAYER(l) (196608 + (size_t)(l) * 786432)
#define WT_QKV_OFF  0
#define WT_WO_OFF   196608
#define WT_FF1_OFF  (196608 + 65536)
#define WT_FF2_OFF  (196608 + 65536 + 262144)
__device__ __nv_bfloat16 g_wt_hi[2555904];
__device__ __nv_bfloat16 g_wt_lo[2555904];

// ---------------- helpers --------------------------------------------------
__device__ __forceinline__ uint32_t smem_u32(const void* p) {
    uint32_t a;
    asm("{ .reg .u64 t; cvta.to.shared.u64 t, %1; cvt.u32.u64 %0, t; }" : "=r"(a) : "l"(p));
    return a;
}
__device__ __forceinline__ float geluf(float v) {
    return 0.5f * v * (1.0f + erff(v * 0.7071067811865476f));
}
__device__ __forceinline__ float blockReduceSum(float v, float* sh) {
    int lane = threadIdx.x & 31, w = threadIdx.x >> 5;
    #pragma unroll
    for (int o = 16; o > 0; o >>= 1) v += __shfl_down_sync(0xffffffffu, v, o);
    __syncthreads();
    if (lane == 0) sh[w] = v;
    __syncthreads();
    if (w == 0) {
        int nw = blockDim.x >> 5;
        float t = (lane < nw) ? sh[lane] : 0.0f;
        #pragma unroll
        for (int o = 16; o > 0; o >>= 1) t += __shfl_down_sync(0xffffffffu, t, o);
        if (lane == 0) sh[0] = t;
    }
    __syncthreads();
    return sh[0];
}

#define LDMATRIX_X4(r0, r1, r2, r3, a) \
    asm volatile("ldmatrix.sync.aligned.m8n8.x4.shared.b16 {%0,%1,%2,%3}, [%4];" \
                 : "=r"(r0), "=r"(r1), "=r"(r2), "=r"(r3) : "r"(a))
#define LDMATRIX_X2(r0, r1, a) \
    asm volatile("ldmatrix.sync.aligned.m8n8.x2.shared.b16 {%0,%1}, [%2];" \
                 : "=r"(r0), "=r"(r1) : "r"(a))
#define LDMATRIX_X2_TRANS(r0, r1, a) \
    asm volatile("ldmatrix.sync.aligned.m8n8.x2.trans.shared.b16 {%0,%1}, [%2];" \
                 : "=r"(r0), "=r"(r1) : "r"(a))
#define MMA_BF16(c, a, b) \
    asm volatile("mma.sync.aligned.m16n8k16.row.col.f32.bf16.bf16.f32 " \
                 "{%0,%1,%2,%3}, {%4,%5,%6,%7}, {%8,%9}, {%0,%1,%2,%3};" \
                 : "+f"((c)[0]), "+f"((c)[1]), "+f"((c)[2]), "+f"((c)[3]) \
                 : "r"((a)[0]), "r"((a)[1]), "r"((a)[2]), "r"((a)[3]), \
                   "r"((b)[0]), "r"((b)[1]))

// ---------------- bias build ------------------------------------------------
__global__ void zero_kernel(float4* p, size_t n4) {
    size_t stride = (size_t)gridDim.x * blockDim.x;
    for (size_t i = (size_t)blockIdx.x * blockDim.x + threadIdx.x; i < n4; i += stride)
        p[i] = make_float4(0.f, 0.f, 0.f, 0.f);
}
__global__ void scatter_kernel(const int* __restrict__ edge_index,
                               const int* __restrict__ edge_type,
                               const float* __restrict__ edge_weight,
                               const float* __restrict__ et_emb,
                               float* __restrict__ bias) {
    int t = blockIdx.x * blockDim.x + threadIdx.x;
    if (t >= NB * NE) return;
    int b = t / NE, e = t % NE;
    int src = edge_index[(size_t)b * 2 * NE + e];
    int dst = edge_index[(size_t)b * 2 * NE + NE + e];
    int et  = edge_type[(size_t)b * NE + e];
    float w = edge_weight[(size_t)b * NE + e];
    float add = (et == 2) ? w : 0.0f;
    size_t base = (size_t)b * NH * NN * NN + (size_t)src * NN + dst;
    #pragma unroll
    for (int h = 0; h < NH; h++)
        atomicAdd(&bias[base + (size_t)h * NN * NN], et_emb[et * NH + h] + add);
}

// --------- weight transpose + bf16 split: out[n][k] = split(W[k][n]) --------
__global__ void split_kernel(const float* __restrict__ W,
                             __nv_bfloat16* __restrict__ hi, __nv_bfloat16* __restrict__ lo,
                             int K, int Nc) {
    __shared__ float t[32][33];
    int n0 = blockIdx.x * 32, k0 = blockIdx.y * 32;
    int x = threadIdx.x, y = threadIdx.y;   // 32 x 8
    #pragma unroll
    for (int i = y; i < 32; i += 8) t[i][x] = W[(size_t)(k0 + i) * Nc + n0 + x];
    __syncthreads();
    #pragma unroll
    for (int i = y; i < 32; i += 8) {
        float v = t[x][i];
        __nv_bfloat16 h = __float2bfloat16_rn(v);
        float l = v - __bfloat162float(h);
        size_t o = (size_t)(n0 + i) * K + k0 + x;
        hi[o] = h;
        lo[o] = __float2bfloat16_rn(l);
    }
}

// ---------------- split-bf16 mma.sync GEMM ----------------------------------
// C[M,Nc] = act(A[M,K] @ Wt[Nc,K]^T + bias), fp32-accurate via hi/lo split.
// Block tile 128x64, K-chunk 32, 256 threads (8 warps), warp tile 32x32.
#define ASTR 40   // bf16 row stride in smem (80B, conflict-free for ldmatrix)
template <int ACT>
__global__ void mma_gemm_kernel(const float* __restrict__ A,
                                const __nv_bfloat16* __restrict__ Whi,
                                const __nv_bfloat16* __restrict__ Wlo,
                                const float* __restrict__ bias, float* __restrict__ C,
                                int K, int Nc) {
    __shared__ __nv_bfloat16 sAh[128 * ASTR], sAl[128 * ASTR];
    __shared__ __nv_bfloat16 sBh[64 * ASTR],  sBl[64 * ASTR];
    int tid = threadIdx.x;
    int warp = tid >> 5, lane = tid & 31;
    int wm = warp & 3, wn = warp >> 2;          // warp tile (wm*32, wn*32)
    int bm = blockIdx.y * 128, bn = blockIdx.x * 64;

    float acc[2][4][4];
    #pragma unroll
    for (int i = 0; i < 2; i++)
        #pragma unroll
        for (int j = 0; j < 4; j++)
            #pragma unroll
            for (int q = 0; q < 4; q++) acc[i][j][q] = 0.f;

    // fill pointers
    int arow = tid >> 1, ahalf = tid & 1;
    const float* ap = A + (size_t)(bm + arow) * K + ahalf * 16;
    int brow = tid >> 2, bseg = tid & 3;
    const __nv_bfloat16* bph = Whi + (size_t)(bn + brow) * K + bseg * 8;
    const __nv_bfloat16* bpl = Wlo + (size_t)(bn + brow) * K + bseg * 8;

    uint32_t uAh = smem_u32(sAh), uAl = smem_u32(sAl);
    uint32_t uBh = smem_u32(sBh), uBl = smem_u32(sBl);

    // ldmatrix per-lane address components (element offsets within tile)
    int a_r = (lane & 7) + ((lane >> 3) & 1) * 8;   // row within 16
    int a_c = (lane >> 4) * 8;                      // k-col within 16
    int ll = lane & 15;
    int b_r = ll & 7;                               // row within 8
    int b_c = (ll >> 3) * 8;                        // k-col within 16

    for (int k0 = 0; k0 < K; k0 += 32) {
        // ---- fill A (split on the fly): 128 rows x 32 floats ----
        #pragma unroll
        for (int j = 0; j < 4; j++) {
            float4 v = *(const float4*)(ap + k0 + j * 4);
            __nv_bfloat162 h0 = __floats2bfloat162_rn(v.x, v.y);
            __nv_bfloat162 h1 = __floats2bfloat162_rn(v.z, v.w);
            __nv_bfloat162 l0 = __floats2bfloat162_rn(v.x - __low2float(h0), v.y - __high2float(h0));
            __nv_bfloat162 l1 = __floats2bfloat162_rn(v.z - __low2float(h1), v.w - __high2float(h1));
            int e = arow * ASTR + ahalf * 16 + j * 4;
            *(__nv_bfloat162*)(sAh + e) = h0; *(__nv_bfloat162*)(sAh + e + 2) = h1;
            *(__nv_bfloat162*)(sAl + e) = l0; *(__nv_bfloat162*)(sAl + e + 2) = l1;
        }
        // ---- fill B: 64 rows x 32 bf16 (pre-split) ----
        {
            int e = brow * ASTR + bseg * 8;
            *(uint4*)(sBh + e) = *(const uint4*)(bph + k0);
            *(uint4*)(sBl + e) = *(const uint4*)(bpl + k0);
        }
        __syncthreads();

        #pragma unroll
        for (int s = 0; s < 32; s += 16) {
            uint32_t ah[2][4], al[2][4], bh[4][2], bl[4][2];
            #pragma unroll
            for (int mi = 0; mi < 2; mi++) {
                int off = ((wm * 32 + mi * 16 + a_r) * ASTR + s + a_c) * 2;
                LDMATRIX_X4(ah[mi][0], ah[mi][1], ah[mi][2], ah[mi][3], uAh + off);
                LDMATRIX_X4(al[mi][0], al[mi][1], al[mi][2], al[mi][3], uAl + off);
            }
            #pragma unroll
            for (int ni = 0; ni < 4; ni++) {
                int off = ((wn * 32 + ni * 8 + b_r) * ASTR + s + b_c) * 2;
                LDMATRIX_X2(bh[ni][0], bh[ni][1], uBh + off);
                LDMATRIX_X2(bl[ni][0], bl[ni][1], uBl + off);
            }
            #pragma unroll
            for (int mi = 0; mi < 2; mi++)
                #pragma unroll
                for (int ni = 0; ni < 4; ni++) {
                    MMA_BF16(acc[mi][ni], ah[mi], bh[ni]);
                    MMA_BF16(acc[mi][ni], ah[mi], bl[ni]);
                    MMA_BF16(acc[mi][ni], al[mi], bh[ni]);
                }
        }
        __syncthreads();
    }

    // ---- epilogue ----
    int gid = lane >> 2, tid2 = (lane & 3) * 2;
    #pragma unroll
    for (int mi = 0; mi < 2; mi++) {
        #pragma unroll
        for (int ni = 0; ni < 4; ni++) {
            int row = bm + wm * 32 + mi * 16 + gid;
            int col = bn + wn * 32 + ni * 8 + tid2;
            float b0 = bias[col], b1 = bias[col + 1];
            float v0 = acc[mi][ni][0] + b0, v1 = acc[mi][ni][1] + b1;
            float v2 = acc[mi][ni][2] + b0, v3 = acc[mi][ni][3] + b1;
            if (ACT == 1) { v0 = geluf(v0); v1 = geluf(v1); v2 = geluf(v2); v3 = geluf(v3); }
            *(float2*)&C[(size_t)row * Nc + col] = make_float2(v0, v1);
            *(float2*)&C[(size_t)(row + 8) * Nc + col] = make_float2(v2, v3);
        }
    }
}

// ---------------- attention (flash-style, tensor-core) ----------------------
// Block = (b,h, 64-row q-tile). 128 threads, 4 warps, warp = 16 q-rows.
// S = QK^T via split-bf16 (3 MMAs); P·V in plain bf16; V via ldmatrix.trans.
__global__ void attn_mma_kernel(const float* __restrict__ qkv,
                                const float* __restrict__ bias,
                                const int* __restrict__ node_mask,
                                float* __restrict__ outp) {
    __shared__ __nv_bfloat16 sQh[64 * ASTR], sQl[64 * ASTR];
    __shared__ __nv_bfloat16 sKh[64 * ASTR], sKl[64 * ASTR];
    __shared__ __nv_bfloat16 sV [64 * ASTR];
    __shared__ float maskb[64];

    int bh = blockIdx.y, b = bh >> 3, h = bh & 7;
    int i0 = blockIdx.x * 64;
    int tid = threadIdx.x, warp = tid >> 5, lane = tid & 31;
    int gid = lane >> 2, qd = lane & 3, ll = lane & 15;
    const float scale = 0.17677669529663687f;   // 1/sqrt(32)

    // load Q (64 x 32) with hi/lo split
    {
        int row = tid >> 1, halfq = tid & 1;
        const float* qp = qkv + ((size_t)(b * NN + i0 + row)) * (3 * DM) + h * HDIM + halfq * 16;
        #pragma unroll
        for (int j = 0; j < 4; j++) {
            float4 v = *(const float4*)(qp + j * 4);
            __nv_bfloat162 h0 = __floats2bfloat162_rn(v.x, v.y);
            __nv_bfloat162 h1 = __floats2bfloat162_rn(v.z, v.w);
            __nv_bfloat162 l0 = __floats2bfloat162_rn(v.x - __low2float(h0), v.y - __high2float(h0));
            __nv_bfloat162 l1 = __floats2bfloat162_rn(v.z - __low2float(h1), v.w - __high2float(h1));
            int e = row * ASTR + halfq * 16 + j * 4;
            *(__nv_bfloat162*)(sQh + e) = h0; *(__nv_bfloat162*)(sQh + e + 2) = h1;
            *(__nv_bfloat162*)(sQl + e) = l0; *(__nv_bfloat162*)(sQl + e + 2) = l1;
        }
    }

    float m0 = -INFINITY, m1 = -INFINITY, l0 = 0.f, l1 = 0.f;
    float oc[4][4];
    #pragma unroll
    for (int i = 0; i < 4; i++)
        #pragma unroll
        for (int j = 0; j < 4; j++) oc[i][j] = 0.f;

    int a_r = (lane & 7) + ((lane >> 3) & 1) * 8;
    int a_c = (lane >> 4) * 8;
    int b_r = ll & 7, b_c = (ll >> 3) * 8;

    uint32_t uQh = smem_u32(sQh), uQl = smem_u32(sQl);
    uint32_t uKh = smem_u32(sKh), uKl = smem_u32(sKl), uV = smem_u32(sV);

    int grow = i0 + warp * 16 + gid;
    const float* brow0 = bias + ((size_t)bh * NN + grow) * NN;
    const float* brow1 = brow0 + 8 * NN;

    for (int j0 = 0; j0 < NN; j0 += 64) {
        __syncthreads();
        // load K (split) + V (plain) chunk
        {
            int row = tid >> 1, halfq = tid & 1;
            const float* kp = qkv + ((size_t)(b * NN + j0 + row)) * (3 * DM) + DM + h * HDIM + halfq * 16;
            const float* vp = kp + DM;
            #pragma unroll
            for (int j = 0; j < 4; j++) {
                float4 v = *(const float4*)(kp + j * 4);
                __nv_bfloat162 h0 = __floats2bfloat162_rn(v.x, v.y);
                __nv_bfloat162 h1 = __floats2bfloat162_rn(v.z, v.w);
                __nv_bfloat162 l0 = __floats2bfloat162_rn(v.x - __low2float(h0), v.y - __high2float(h0));
                __nv_bfloat162 l1 = __floats2bfloat162_rn(v.z - __low2float(h1), v.w - __high2float(h1));
                int e = row * ASTR + halfq * 16 + j * 4;
                *(__nv_bfloat162*)(sKh + e) = h0; *(__nv_bfloat162*)(sKh + e + 2) = h1;
                *(__nv_bfloat162*)(sKl + e) = l0; *(__nv_bfloat162*)(sKl + e + 2) = l1;
                float4 vv = *(const float4*)(vp + j * 4);
                *(__nv_bfloat162*)(sV + e)     = __floats2bfloat162_rn(vv.x, vv.y);
                *(__nv_bfloat162*)(sV + e + 2) = __floats2bfloat162_rn(vv.z, vv.w);
            }
        }
        if (tid < 64) maskb[tid] = node_mask[b * NN + j0 + tid] ? 0.f : -INFINITY;
        __syncthreads();

        // Q fragments (2 k-steps)
        uint32_t qh[2][4], ql[2][4];
        #pragma unroll
        for (int s = 0; s < 2; s++) {
            int off = ((warp * 16 + a_r) * ASTR + s * 16 + a_c) * 2;
            LDMATRIX_X4(qh[s][0], qh[s][1], qh[s][2], qh[s][3], uQh + off);
            LDMATRIX_X4(ql[s][0], ql[s][1], ql[s][2], ql[s][3], uQl + off);
        }
        // S = QK^T (split, 3 MMAs per k-step)
        float sc[8][4];
        #pragma unroll
        for (int ni = 0; ni < 8; ni++) {
            sc[ni][0] = sc[ni][1] = sc[ni][2] = sc[ni][3] = 0.f;
            #pragma unroll
            for (int s = 0; s < 2; s++) {
                uint32_t kh[2], kl[2];
                int off = ((ni * 8 + b_r) * ASTR + s * 16 + b_c) * 2;
                LDMATRIX_X2(kh[0], kh[1], uKh + off);
                LDMATRIX_X2(kl[0], kl[1], uKl + off);
                MMA_BF16(sc[ni], qh[s], kh);
                MMA_BF16(sc[ni], qh[s], kl);
                MMA_BF16(sc[ni], ql[s], kh);
            }
        }
        // scale + bias + mask, row maxes
        float mx0 = -INFINITY, mx1 = -INFINITY;
        #pragma unroll
        for (int ni = 0; ni < 8; ni++) {
            int col = ni * 8 + qd * 2;
            float2 bv0 = *(const float2*)(brow0 + j0 + col);
            float2 bv1 = *(const float2*)(brow1 + j0 + col);
            sc[ni][0] = sc[ni][0] * scale + bv0.x + maskb[col];
            sc[ni][1] = sc[ni][1] * scale + bv0.y + maskb[col + 1];
            sc[ni][2] = sc[ni][2] * scale + bv1.x + maskb[col];
            sc[ni][3] = sc[ni][3] * scale + bv1.y + maskb[col + 1];
            mx0 = fmaxf(mx0, fmaxf(sc[ni][0], sc[ni][1]));
            mx1 = fmaxf(mx1, fmaxf(sc[ni][2], sc[ni][3]));
        }
        mx0 = fmaxf(mx0, __shfl_xor_sync(0xffffffffu, mx0, 1));
        mx0 = fmaxf(mx0, __shfl_xor_sync(0xffffffffu, mx0, 2));
        mx1 = fmaxf(mx1, __shfl_xor_sync(0xffffffffu, mx1, 1));
        mx1 = fmaxf(mx1, __shfl_xor_sync(0xffffffffu, mx1, 2));

        float mn0 = fmaxf(m0, mx0), mn1 = fmaxf(m1, mx1);
        float c0 = (mn0 == -INFINITY) ? 1.f : __expf(m0 - mn0);
        float c1 = (mn1 == -INFINITY) ? 1.f : __expf(m1 - mn1);
        float ls0 = 0.f, ls1 = 0.f;
        #pragma unroll
        for (int ni = 0; ni < 8; ni++) {
            float p0 = (sc[ni][0] == -INFINITY) ? 0.f : __expf(sc[ni][0] - mn0);
            float p1 = (sc[ni][1] == -INFINITY) ? 0.f : __expf(sc[ni][1] - mn0);
            float p2 = (sc[ni][2] == -INFINITY) ? 0.f : __expf(sc[ni][2] - mn1);
            float p3 = (sc[ni][3] == -INFINITY) ? 0.f : __expf(sc[ni][3] - mn1);
            sc[ni][0] = p0; sc[ni][1] = p1; sc[ni][2] = p2; sc[ni][3] = p3;
            ls0 += p0 + p1; ls1 += p2 + p3;
        }
        ls0 += __shfl_xor_sync(0xffffffffu, ls0, 1);
        ls0 += __shfl_xor_sync(0xffffffffu, ls0, 2);
        ls1 += __shfl_xor_sync(0xffffffffu, ls1, 1);
        ls1 += __shfl_xor_sync(0xffffffffu, ls1, 2);
        l0 = l0 * c0 + ls0;
        l1 = l1 * c1 + ls1;
        #pragma unroll
        for (int ni = 0; ni < 4; ni++) {
            oc[ni][0] *= c0; oc[ni][1] *= c0;
            oc[ni][2] *= c1; oc[ni][3] *= c1;
        }
        m0 = mn0; m1 = mn1;

        // P·V: C-fragments of S pack directly into A-fragments
        #pragma unroll
        for (int ks = 0; ks < 4; ks++) {
            uint32_t pa[4];
            __nv_bfloat162 t0 = __floats2bfloat162_rn(sc[2*ks][0], sc[2*ks][1]);
            __nv_bfloat162 t1 = __floats2bfloat162_rn(sc[2*ks][2], sc[2*ks][3]);
            __nv_bfloat162 t2 = __floats2bfloat162_rn(sc[2*ks+1][0], sc[2*ks+1][1]);
            __nv_bfloat162 t3 = __floats2bfloat162_rn(sc[2*ks+1][2], sc[2*ks+1][3]);
            pa[0] = *(uint32_t*)&t0; pa[1] = *(uint32_t*)&t1;
            pa[2] = *(uint32_t*)&t2; pa[3] = *(uint32_t*)&t3;
            #pragma unroll
            for (int ni = 0; ni < 4; ni++) {
                uint32_t vb[2];
                int off = ((ks * 16 + ll) * ASTR + ni * 8) * 2;
                LDMATRIX_X2_TRANS(vb[0], vb[1], uV + off);
                MMA_BF16(oc[ni], pa, vb);
            }
        }
    }

    float inv0 = (l0 > 0.f) ? 1.f / l0 : 0.f;
    float inv1 = (l1 > 0.f) ? 1.f / l1 : 0.f;
    float* op0 = outp + ((size_t)(b * NN + grow)) * DM + h * HDIM;
    float* op1 = op0 + 8 * DM;
    #pragma unroll
    for (int ni = 0; ni < 4; ni++) {
        int col = ni * 8 + qd * 2;
        *(float2*)(op0 + col) = make_float2(oc[ni][0] * inv0, oc[ni][1] * inv0);
        *(float2*)(op1 + col) = make_float2(oc[ni][2] * inv1, oc[ni][3] * inv1);
    }
}

// ---------------- residual + LayerNorm -------------------------------------
__global__ void add_ln_kernel(const float* __restrict__ xin, const float* __restrict__ res,
                              const float* __restrict__ g, const float* __restrict__ bb,
                              float* __restrict__ xout) {
    __shared__ float red[32];
    int row = blockIdx.x, tid = threadIdx.x;
    float v = xin[(size_t)row * DM + tid] + res[(size_t)row * DM + tid];
    float mu = blockReduceSum(v, red) * (1.0f / DM);
    float c = v - mu;
    float var = blockReduceSum(c * c, red) * (1.0f / DM);
    xout[(size_t)row * DM + tid] = c * rsqrtf(var + 1e-5f) * g[tid] + bb[tid];
}

// ---------------- pooling + MLP head ---------------------------------------
__global__ void head_kernel(const float* __restrict__ x,
                            const int* __restrict__ tmask, const int* __restrict__ imask,
                            const int* __restrict__ gidx,
                            const float* __restrict__ Wm1, const float* __restrict__ bm1,
                            const float* __restrict__ Wm2, const float* __restrict__ bm2,
                            const float* __restrict__ Wm3, const float* __restrict__ bm3,
                            float* __restrict__ out) {
    __shared__ float red[32];
    __shared__ float comb[769];
    __shared__ float h1[512];
    __shared__ float h2[256];
    int b = blockIdx.x, tid = threadIdx.x;

    float tcp = 0.f, icp = 0.f;
    for (int n = tid; n < NN; n += 256) {
        tcp += (tmask[b * NN + n] != 0) ? 1.f : 0.f;
        icp += (imask[b * NN + n] != 0) ? 1.f : 0.f;
    }
    float tc = fmaxf(blockReduceSum(tcp, red), 1.f);
    float ic = fmaxf(blockReduceSum(icp, red), 1.f);

    int d = tid;
    float tp = 0.f, ip = 0.f;
    for (int n = 0; n < NN; n++) {
        float v = x[((size_t)(b * NN + n)) * DM + d];
        if (tmask[b * NN + n] != 0) tp += v;
        if (imask[b * NN + n] != 0) ip += v;
    }
    tp /= tc; ip /= ic;
    int gi = gidx[b];
    float ge = x[((size_t)(b * NN + gi)) * DM + d];

    float n1s = blockReduceSum(tp * tp, red);
    float n2s = blockReduceSum(ip * ip, red);
    float dt  = blockReduceSum(tp * ip, red);
    float n1 = fmaxf(sqrtf(n1s), 1e-6f), n2 = fmaxf(sqrtf(n2s), 1e-6f);
    float conflict = 1.f - dt / (n1 * n2);

    comb[d] = ge; comb[256 + d] = tp; comb[512 + d] = ip;
    if (tid == 0) comb[768] = conflict;
    __syncthreads();

    for (int j = tid; j < 512; j += 256) {
        float a = bm1[j];
        for (int i = 0; i < 769; i++) a += comb[i] * Wm1[(size_t)i * 512 + j];
        h1[j] = geluf(a);
    }
    __syncthreads();
    {
        float a = bm2[tid];
        for (int i = 0; i < 512; i++) a += h1[i] * Wm2[(size_t)i * 256 + tid];
        h2[tid] = geluf(a);
    }
    __syncthreads();
    float tot = blockReduceSum(h2[tid] * Wm3[tid], red);
    if (tid == 0) out[b] = tot + bm3[0];
}

// ---------------- launch ----------------------------------------------------
extern "C" void kernel_launch(void* const* d_in, const int* in_sizes, int n_in,
                              void* d_out, int out_size) {
    const float* node_feats = (const float*)d_in[0];
    const int*   node_mask  = (const int*)d_in[1];
    const int*   text_mask  = (const int*)d_in[2];
    const int*   image_mask = (const int*)d_in[3];
    const int*   gidx       = (const int*)d_in[4];
    const int*   edge_index = (const int*)d_in[5];
    const int*   edge_type  = (const int*)d_in[6];
    const float* edge_weight= (const float*)d_in[7];
    const float* W_in  = (const float*)d_in[8];
    const float* b_in  = (const float*)d_in[9];
    const float* Wqkv  = (const float*)d_in[10];
    const float* bqkv  = (const float*)d_in[11];
    const float* Wo    = (const float*)d_in[12];
    const float* bo    = (const float*)d_in[13];
    const float* ln1_g = (const float*)d_in[14];
    const float* ln1_b = (const float*)d_in[15];
    const float* ln2_g = (const float*)d_in[16];
    const float* ln2_b = (const float*)d_in[17];
    const float* Wff1  = (const float*)d_in[18];
    const float* bff1  = (const float*)d_in[19];
    const float* Wff2  = (const float*)d_in[20];
    const float* bff2  = (const float*)d_in[21];
    const float* et_emb= (const float*)d_in[22];
    const float* Wm1   = (const float*)d_in[23];
    const float* bm1   = (const float*)d_in[24];
    const float* Wm2   = (const float*)d_in[25];
    const float* bm2   = (const float*)d_in[26];
    const float* Wm3   = (const float*)d_in[27];
    const float* bm3   = (const float*)d_in[28];

    float *bias, *x, *qkv, *attn, *tmp, *ff;
    __nv_bfloat16 *wth, *wtl;
    cudaGetSymbolAddress((void**)&bias, g_bias);
    cudaGetSymbolAddress((void**)&x,    g_x);
    cudaGetSymbolAddress((void**)&qkv,  g_qkv);
    cudaGetSymbolAddress((void**)&attn, g_attn);
    cudaGetSymbolAddress((void**)&tmp,  g_tmp);
    cudaGetSymbolAddress((void**)&ff,   g_ff);
    cudaGetSymbolAddress((void**)&wth,  g_wt_hi);
    cudaGetSymbolAddress((void**)&wtl,  g_wt_lo);

    // ---- weight transpose + split (W[K,N] -> hi/lo[N,K]) ----
    split_kernel<<<dim3(DM / 32, IND / 32), dim3(32, 8)>>>(W_in, wth + WT_IN_OFF, wtl + WT_IN_OFF, IND, DM);
    for (int l = 0; l < NL; l++) {
        size_t lo = WT_LAYER(l);
        split_kernel<<<dim3(3 * DM / 32, DM / 32), dim3(32, 8)>>>(
            Wqkv + (size_t)l * DM * 3 * DM, wth + lo + WT_QKV_OFF, wtl + lo + WT_QKV_OFF, DM, 3 * DM);
        split_kernel<<<dim3(DM / 32, DM / 32), dim3(32, 8)>>>(
            Wo + (size_t)l * DM * DM, wth + lo + WT_WO_OFF, wtl + lo + WT_WO_OFF, DM, DM);
        split_kernel<<<dim3(FFD / 32, DM / 32), dim3(32, 8)>>>(
            Wff1 + (size_t)l * DM * FFD, wth + lo + WT_FF1_OFF, wtl + lo + WT_FF1_OFF, DM, FFD);
        split_kernel<<<dim3(DM / 32, FFD / 32), dim3(32, 8)>>>(
            Wff2 + (size_t)l * FFD * DM, wth + lo + WT_FF2_OFF, wtl + lo + WT_FF2_OFF, FFD, DM);
    }

    size_t bias_elems = (size_t)NB * NH * NN * NN;
    zero_kernel<<<4096, 256>>>((float4*)bias, bias_elems / 4);
    scatter_kernel<<<(NB * NE + 255) / 256, 256>>>(edge_index, edge_type, edge_weight, et_emb, bias);

    // input projection
    mma_gemm_kernel<0><<<dim3(DM / 64, ROWS / 128), 256>>>(
        node_feats, wth + WT_IN_OFF, wtl + WT_IN_OFF, b_in, x, IND, DM);

    for (int l = 0; l < NL; l++) {
        size_t lo = WT_LAYER(l);
        mma_gemm_kernel<0><<<dim3(3 * DM / 64, ROWS / 128), 256>>>(
            x, wth + lo + WT_QKV_OFF, wtl + lo + WT_QKV_OFF, bqkv + (size_t)l * 3 * DM, qkv, DM, 3 * DM);
        attn_mma_kernel<<<dim3(NN / 64, NB * NH), 128>>>(qkv, bias, node_mask, attn);
        mma_gemm_kernel<0><<<dim3(DM / 64, ROWS / 128), 256>>>(
            attn, wth + lo + WT_WO_OFF, wtl + lo + WT_WO_OFF, bo + (size_t)l * DM, tmp, DM, DM);
        add_ln_kernel<<<ROWS, 256>>>(x, tmp, ln1_g + (size_t)l * DM, ln1_b + (size_t)l * DM, x);
        mma_gemm_kernel<1><<<dim3(FFD / 64, ROWS / 128), 256>>>(
            x, wth + lo + WT_FF1_OFF, wtl + lo + WT_FF1_OFF, bff1 + (size_t)l * FFD, ff, DM, FFD);
        mma_gemm_kernel<0><<<dim3(DM / 64, ROWS / 128), 256>>>(
            ff, wth + lo + WT_FF2_OFF, wtl + lo + WT_FF2_OFF, bff2 + (size_t)l * DM, tmp, FFD, DM);
        add_ln_kernel<<<ROWS, 256>>>(x, tmp, ln2_g + (size_t)l * DM, ln2_b + (size_t)l * DM, x);
    }

    head_kernel<<<NB, 256>>>(x, text_mask, image_mask, gidx,
                             Wm1, bm1, Wm2, bm2, Wm3, bm3, (float*)d_out);
}

// round 14
// speedup vs baseline: 2.9284x; 1.0736x over previous
#include <cuda_runtime.h>
#include <cuda_bf16.h>
#include <math.h>
#include <stdint.h>

#define NB   16
#define NN   512
#define DM   256
#define NH   8
#define HDIM 32
#define NL   3
#define NE   4096
#define IND  768
#define FFD  1024
#define ROWS (NB*NN)   // 8192

// ---------------- scratch (device globals; no allocation allowed) ----------
__device__ float g_bias[(size_t)NB*NH*NN*NN];   // 134 MB attn bias (B,H,N,N)
__device__ float g_x   [(size_t)ROWS*DM];
__device__ float g_qkv [(size_t)ROWS*3*DM];
__device__ float g_attn[(size_t)ROWS*DM];
__device__ float g_tmp [(size_t)ROWS*DM];
__device__ float g_ff  [(size_t)ROWS*FFD];
// transposed + split weights, [N][K] layout, bf16 hi/lo
#define WT_IN_OFF   0
#define WT_LAYER(l) (196608 + (size_t)(l) * 786432)
#define WT_QKV_OFF  0
#define WT_WO_OFF   196608
#define WT_FF1_OFF  (196608 + 65536)
#define WT_FF2_OFF  (196608 + 65536 + 262144)
__device__ __nv_bfloat16 g_wt_hi[2555904];
__device__ __nv_bfloat16 g_wt_lo[2555904];

// ---------------- helpers --------------------------------------------------
__device__ __forceinline__ uint32_t smem_u32(const void* p) {
    uint32_t a;
    asm("{ .reg .u64 t; cvta.to.shared.u64 t, %1; cvt.u32.u64 %0, t; }" : "=r"(a) : "l"(p));
    return a;
}
__device__ __forceinline__ float geluf(float v) {
    return 0.5f * v * (1.0f + erff(v * 0.7071067811865476f));
}
__device__ __forceinline__ float blockReduceSum(float v, float* sh) {
    int lane = threadIdx.x & 31, w = threadIdx.x >> 5;
    #pragma unroll
    for (int o = 16; o > 0; o >>= 1) v += __shfl_down_sync(0xffffffffu, v, o);
    __syncthreads();
    if (lane == 0) sh[w] = v;
    __syncthreads();
    if (w == 0) {
        int nw = blockDim.x >> 5;
        float t = (lane < nw) ? sh[lane] : 0.0f;
        #pragma unroll
        for (int o = 16; o > 0; o >>= 1) t += __shfl_down_sync(0xffffffffu, t, o);
        if (lane == 0) sh[0] = t;
    }
    __syncthreads();
    return sh[0];
}

#define LDMATRIX_X4(r0, r1, r2, r3, a) \
    asm volatile("ldmatrix.sync.aligned.m8n8.x4.shared.b16 {%0,%1,%2,%3}, [%4];" \
                 : "=r"(r0), "=r"(r1), "=r"(r2), "=r"(r3) : "r"(a))
#define LDMATRIX_X2(r0, r1, a) \
    asm volatile("ldmatrix.sync.aligned.m8n8.x2.shared.b16 {%0,%1}, [%2];" \
                 : "=r"(r0), "=r"(r1) : "r"(a))
#define LDMATRIX_X2_TRANS(r0, r1, a) \
    asm volatile("ldmatrix.sync.aligned.m8n8.x2.trans.shared.b16 {%0,%1}, [%2];" \
                 : "=r"(r0), "=r"(r1) : "r"(a))
#define MMA_BF16(c, a, b) \
    asm volatile("mma.sync.aligned.m16n8k16.row.col.f32.bf16.bf16.f32 " \
                 "{%0,%1,%2,%3}, {%4,%5,%6,%7}, {%8,%9}, {%0,%1,%2,%3};" \
                 : "+f"((c)[0]), "+f"((c)[1]), "+f"((c)[2]), "+f"((c)[3]) \
                 : "r"((a)[0]), "r"((a)[1]), "r"((a)[2]), "r"((a)[3]), \
                   "r"((b)[0]), "r"((b)[1]))

// ---------------- bias build ------------------------------------------------
__global__ void zero_kernel(float4* p, size_t n4) {
    size_t stride = (size_t)gridDim.x * blockDim.x;
    for (size_t i = (size_t)blockIdx.x * blockDim.x + threadIdx.x; i < n4; i += stride)
        p[i] = make_float4(0.f, 0.f, 0.f, 0.f);
}
__global__ void scatter_kernel(const int* __restrict__ edge_index,
                               const int* __restrict__ edge_type,
                               const float* __restrict__ edge_weight,
                               const float* __restrict__ et_emb,
                               float* __restrict__ bias) {
    int t = blockIdx.x * blockDim.x + threadIdx.x;
    if (t >= NB * NE) return;
    int b = t / NE, e = t % NE;
    int src = edge_index[(size_t)b * 2 * NE + e];
    int dst = edge_index[(size_t)b * 2 * NE + NE + e];
    int et  = edge_type[(size_t)b * NE + e];
    float w = edge_weight[(size_t)b * NE + e];
    float add = (et == 2) ? w : 0.0f;
    size_t base = (size_t)b * NH * NN * NN + (size_t)src * NN + dst;
    #pragma unroll
    for (int h = 0; h < NH; h++)
        atomicAdd(&bias[base + (size_t)h * NN * NN], et_emb[et * NH + h] + add);
}

// --------- weight transpose + bf16 split (batched over layers via grid.z) ---
__global__ void split_kernel(const float* __restrict__ W,
                             __nv_bfloat16* __restrict__ hi, __nv_bfloat16* __restrict__ lo,
                             int K, int Nc, size_t wStride, size_t tStride) {
    __shared__ float t[32][33];
    int layer = blockIdx.z;
    W  += (size_t)layer * wStride;
    hi += (size_t)layer * tStride;
    lo += (size_t)layer * tStride;
    int n0 = blockIdx.x * 32, k0 = blockIdx.y * 32;
    int x = threadIdx.x, y = threadIdx.y;   // 32 x 8
    #pragma unroll
    for (int i = y; i < 32; i += 8) t[i][x] = W[(size_t)(k0 + i) * Nc + n0 + x];
    __syncthreads();
    #pragma unroll
    for (int i = y; i < 32; i += 8) {
        float v = t[x][i];
        __nv_bfloat16 h = __float2bfloat16_rn(v);
        float l = v - __bfloat162float(h);
        size_t o = (size_t)(n0 + i) * K + k0 + x;
        hi[o] = h;
        lo[o] = __float2bfloat16_rn(l);
    }
}

// ---------------- split-bf16 mma.sync GEMM (software pipelined) -------------
// C[M,Nc] = act(A[M,K] @ Wt[Nc,K]^T + bias), fp32-accurate via hi/lo split.
// Block tile 128x64, K-chunk 32, 256 threads (8 warps), warp tile 32x32.
// Next chunk's global loads are register-prefetched during current compute.
#define ASTR 40   // bf16 row stride in smem (80B, conflict-free for ldmatrix)
template <int ACT>
__global__ void mma_gemm_kernel(const float* __restrict__ A,
                                const __nv_bfloat16* __restrict__ Whi,
                                const __nv_bfloat16* __restrict__ Wlo,
                                const float* __restrict__ bias, float* __restrict__ C,
                                int K, int Nc) {
    __shared__ __nv_bfloat16 sAh[128 * ASTR], sAl[128 * ASTR];
    __shared__ __nv_bfloat16 sBh[64 * ASTR],  sBl[64 * ASTR];
    int tid = threadIdx.x;
    int warp = tid >> 5, lane = tid & 31;
    int wm = warp & 3, wn = warp >> 2;          // warp tile (wm*32, wn*32)
    int bm = blockIdx.y * 128, bn = blockIdx.x * 64;

    float acc[2][4][4];
    #pragma unroll
    for (int i = 0; i < 2; i++)
        #pragma unroll
        for (int j = 0; j < 4; j++)
            #pragma unroll
            for (int q = 0; q < 4; q++) acc[i][j][q] = 0.f;

    // fill pointers
    int arow = tid >> 1, ahalf = tid & 1;
    const float* ap = A + (size_t)(bm + arow) * K + ahalf * 16;
    int brow = tid >> 2, bseg = tid & 3;
    const __nv_bfloat16* bph = Whi + (size_t)(bn + brow) * K + bseg * 8;
    const __nv_bfloat16* bpl = Wlo + (size_t)(bn + brow) * K + bseg * 8;

    uint32_t uAh = smem_u32(sAh), uAl = smem_u32(sAl);
    uint32_t uBh = smem_u32(sBh), uBl = smem_u32(sBl);

    // ldmatrix per-lane address components (element offsets within tile)
    int a_r = (lane & 7) + ((lane >> 3) & 1) * 8;   // row within 16
    int a_c = (lane >> 4) * 8;                      // k-col within 16
    int ll = lane & 15;
    int b_r = ll & 7;                               // row within 8
    int b_c = (ll >> 3) * 8;                        // k-col within 16

    int nchunks = K >> 5;

    // register prefetch buffers
    float4 aR[4];
    uint4 bRh, bRl;
    #pragma unroll
    for (int j = 0; j < 4; j++) aR[j] = *(const float4*)(ap + j * 4);
    bRh = *(const uint4*)bph;
    bRl = *(const uint4*)bpl;

    for (int c = 0; c < nchunks; c++) {
        // ---- store prefetched regs -> smem (split A on the fly) ----
        #pragma unroll
        for (int j = 0; j < 4; j++) {
            float4 v = aR[j];
            __nv_bfloat162 h0 = __floats2bfloat162_rn(v.x, v.y);
            __nv_bfloat162 h1 = __floats2bfloat162_rn(v.z, v.w);
            __nv_bfloat162 l0 = __floats2bfloat162_rn(v.x - __low2float(h0), v.y - __high2float(h0));
            __nv_bfloat162 l1 = __floats2bfloat162_rn(v.z - __low2float(h1), v.w - __high2float(h1));
            int e = arow * ASTR + ahalf * 16 + j * 4;
            *(__nv_bfloat162*)(sAh + e) = h0; *(__nv_bfloat162*)(sAh + e + 2) = h1;
            *(__nv_bfloat162*)(sAl + e) = l0; *(__nv_bfloat162*)(sAl + e + 2) = l1;
        }
        {
            int e = brow * ASTR + bseg * 8;
            *(uint4*)(sBh + e) = bRh;
            *(uint4*)(sBl + e) = bRl;
        }
        __syncthreads();

        // ---- issue next chunk's global loads (latency hidden by compute) ----
        if (c + 1 < nchunks) {
            int k1 = (c + 1) << 5;
            #pragma unroll
            for (int j = 0; j < 4; j++) aR[j] = *(const float4*)(ap + k1 + j * 4);
            bRh = *(const uint4*)(bph + k1);
            bRl = *(const uint4*)(bpl + k1);
        }

        // ---- compute current chunk ----
        #pragma unroll
        for (int s = 0; s < 32; s += 16) {
            uint32_t ah[2][4], al[2][4], bh[4][2], bl[4][2];
            #pragma unroll
            for (int mi = 0; mi < 2; mi++) {
                int off = ((wm * 32 + mi * 16 + a_r) * ASTR + s + a_c) * 2;
                LDMATRIX_X4(ah[mi][0], ah[mi][1], ah[mi][2], ah[mi][3], uAh + off);
                LDMATRIX_X4(al[mi][0], al[mi][1], al[mi][2], al[mi][3], uAl + off);
            }
            #pragma unroll
            for (int ni = 0; ni < 4; ni++) {
                int off = ((wn * 32 + ni * 8 + b_r) * ASTR + s + b_c) * 2;
                LDMATRIX_X2(bh[ni][0], bh[ni][1], uBh + off);
                LDMATRIX_X2(bl[ni][0], bl[ni][1], uBl + off);
            }
            #pragma unroll
            for (int mi = 0; mi < 2; mi++)
                #pragma unroll
                for (int ni = 0; ni < 4; ni++) {
                    MMA_BF16(acc[mi][ni], ah[mi], bh[ni]);
                    MMA_BF16(acc[mi][ni], ah[mi], bl[ni]);
                    MMA_BF16(acc[mi][ni], al[mi], bh[ni]);
                }
        }
        __syncthreads();
    }

    // ---- epilogue ----
    int gid = lane >> 2, tid2 = (lane & 3) * 2;
    #pragma unroll
    for (int mi = 0; mi < 2; mi++) {
        #pragma unroll
        for (int ni = 0; ni < 4; ni++) {
            int row = bm + wm * 32 + mi * 16 + gid;
            int col = bn + wn * 32 + ni * 8 + tid2;
            float b0 = bias[col], b1 = bias[col + 1];
            float v0 = acc[mi][ni][0] + b0, v1 = acc[mi][ni][1] + b1;
            float v2 = acc[mi][ni][2] + b0, v3 = acc[mi][ni][3] + b1;
            if (ACT == 1) { v0 = geluf(v0); v1 = geluf(v1); v2 = geluf(v2); v3 = geluf(v3); }
            *(float2*)&C[(size_t)row * Nc + col] = make_float2(v0, v1);
            *(float2*)&C[(size_t)(row + 8) * Nc + col] = make_float2(v2, v3);
        }
    }
}

// ---------------- attention (flash-style, tensor-core) ----------------------
// Block = (b,h, 64-row q-tile). 128 threads, 4 warps, warp = 16 q-rows.
// S = QK^T via split-bf16 (3 MMAs); P·V in plain bf16; V via ldmatrix.trans.
__global__ void attn_mma_kernel(const float* __restrict__ qkv,
                                const float* __restrict__ bias,
                                const int* __restrict__ node_mask,
                                float* __restrict__ outp) {
    __shared__ __nv_bfloat16 sQh[64 * ASTR], sQl[64 * ASTR];
    __shared__ __nv_bfloat16 sKh[64 * ASTR], sKl[64 * ASTR];
    __shared__ __nv_bfloat16 sV [64 * ASTR];
    __shared__ float maskb[64];

    int bh = blockIdx.y, b = bh >> 3, h = bh & 7;
    int i0 = blockIdx.x * 64;
    int tid = threadIdx.x, warp = tid >> 5, lane = tid & 31;
    int gid = lane >> 2, qd = lane & 3, ll = lane & 15;
    const float scale = 0.17677669529663687f;   // 1/sqrt(32)

    // load Q (64 x 32) with hi/lo split
    {
        int row = tid >> 1, halfq = tid & 1;
        const float* qp = qkv + ((size_t)(b * NN + i0 + row)) * (3 * DM) + h * HDIM + halfq * 16;
        #pragma unroll
        for (int j = 0; j < 4; j++) {
            float4 v = *(const float4*)(qp + j * 4);
            __nv_bfloat162 h0 = __floats2bfloat162_rn(v.x, v.y);
            __nv_bfloat162 h1 = __floats2bfloat162_rn(v.z, v.w);
            __nv_bfloat162 l0 = __floats2bfloat162_rn(v.x - __low2float(h0), v.y - __high2float(h0));
            __nv_bfloat162 l1 = __floats2bfloat162_rn(v.z - __low2float(h1), v.w - __high2float(h1));
            int e = row * ASTR + halfq * 16 + j * 4;
            *(__nv_bfloat162*)(sQh + e) = h0; *(__nv_bfloat162*)(sQh + e + 2) = h1;
            *(__nv_bfloat162*)(sQl + e) = l0; *(__nv_bfloat162*)(sQl + e + 2) = l1;
        }
    }

    float m0 = -INFINITY, m1 = -INFINITY, l0 = 0.f, l1 = 0.f;
    float oc[4][4];
    #pragma unroll
    for (int i = 0; i < 4; i++)
        #pragma unroll
        for (int j = 0; j < 4; j++) oc[i][j] = 0.f;

    int a_r = (lane & 7) + ((lane >> 3) & 1) * 8;
    int a_c = (lane >> 4) * 8;
    int b_r = ll & 7, b_c = (ll >> 3) * 8;

    uint32_t uQh = smem_u32(sQh), uQl = smem_u32(sQl);
    uint32_t uKh = smem_u32(sKh), uKl = smem_u32(sKl), uV = smem_u32(sV);

    int grow = i0 + warp * 16 + gid;
    const float* brow0 = bias + ((size_t)bh * NN + grow) * NN;
    const float* brow1 = brow0 + 8 * NN;

    for (int j0 = 0; j0 < NN; j0 += 64) {
        __syncthreads();
        // load K (split) + V (plain) chunk
        {
            int row = tid >> 1, halfq = tid & 1;
            const float* kp = qkv + ((size_t)(b * NN + j0 + row)) * (3 * DM) + DM + h * HDIM + halfq * 16;
            const float* vp = kp + DM;
            #pragma unroll
            for (int j = 0; j < 4; j++) {
                float4 v = *(const float4*)(kp + j * 4);
                __nv_bfloat162 h0 = __floats2bfloat162_rn(v.x, v.y);
                __nv_bfloat162 h1 = __floats2bfloat162_rn(v.z, v.w);
                __nv_bfloat162 l0 = __floats2bfloat162_rn(v.x - __low2float(h0), v.y - __high2float(h0));
                __nv_bfloat162 l1 = __floats2bfloat162_rn(v.z - __low2float(h1), v.w - __high2float(h1));
                int e = row * ASTR + halfq * 16 + j * 4;
                *(__nv_bfloat162*)(sKh + e) = h0; *(__nv_bfloat162*)(sKh + e + 2) = h1;
                *(__nv_bfloat162*)(sKl + e) = l0; *(__nv_bfloat162*)(sKl + e + 2) = l1;
                float4 vv = *(const float4*)(vp + j * 4);
                *(__nv_bfloat162*)(sV + e)     = __floats2bfloat162_rn(vv.x, vv.y);
                *(__nv_bfloat162*)(sV + e + 2) = __floats2bfloat162_rn(vv.z, vv.w);
            }
        }
        if (tid < 64) maskb[tid] = node_mask[b * NN + j0 + tid] ? 0.f : -INFINITY;
        __syncthreads();

        // Q fragments (2 k-steps)
        uint32_t qh[2][4], ql[2][4];
        #pragma unroll
        for (int s = 0; s < 2; s++) {
            int off = ((warp * 16 + a_r) * ASTR + s * 16 + a_c) * 2;
            LDMATRIX_X4(qh[s][0], qh[s][1], qh[s][2], qh[s][3], uQh + off);
            LDMATRIX_X4(ql[s][0], ql[s][1], ql[s][2], ql[s][3], uQl + off);
        }
        // S = QK^T (split, 3 MMAs per k-step)
        float sc[8][4];
        #pragma unroll
        for (int ni = 0; ni < 8; ni++) {
            sc[ni][0] = sc[ni][1] = sc[ni][2] = sc[ni][3] = 0.f;
            #pragma unroll
            for (int s = 0; s < 2; s++) {
                uint32_t kh[2], kl[2];
                int off = ((ni * 8 + b_r) * ASTR + s * 16 + b_c) * 2;
                LDMATRIX_X2(kh[0], kh[1], uKh + off);
                LDMATRIX_X2(kl[0], kl[1], uKl + off);
                MMA_BF16(sc[ni], qh[s], kh);
                MMA_BF16(sc[ni], qh[s], kl);
                MMA_BF16(sc[ni], ql[s], kh);
            }
        }
        // scale + bias + mask, row maxes
        float mx0 = -INFINITY, mx1 = -INFINITY;
        #pragma unroll
        for (int ni = 0; ni < 8; ni++) {
            int col = ni * 8 + qd * 2;
            float2 bv0 = *(const float2*)(brow0 + j0 + col);
            float2 bv1 = *(const float2*)(brow1 + j0 + col);
            sc[ni][0] = sc[ni][0] * scale + bv0.x + maskb[col];
            sc[ni][1] = sc[ni][1] * scale + bv0.y + maskb[col + 1];
            sc[ni][2] = sc[ni][2] * scale + bv1.x + maskb[col];
            sc[ni][3] = sc[ni][3] * scale + bv1.y + maskb[col + 1];
            mx0 = fmaxf(mx0, fmaxf(sc[ni][0], sc[ni][1]));
            mx1 = fmaxf(mx1, fmaxf(sc[ni][2], sc[ni][3]));
        }
        mx0 = fmaxf(mx0, __shfl_xor_sync(0xffffffffu, mx0, 1));
        mx0 = fmaxf(mx0, __shfl_xor_sync(0xffffffffu, mx0, 2));
        mx1 = fmaxf(mx1, __shfl_xor_sync(0xffffffffu, mx1, 1));
        mx1 = fmaxf(mx1, __shfl_xor_sync(0xffffffffu, mx1, 2));

        float mn0 = fmaxf(m0, mx0), mn1 = fmaxf(m1, mx1);
        float c0 = (mn0 == -INFINITY) ? 1.f : __expf(m0 - mn0);
        float c1 = (mn1 == -INFINITY) ? 1.f : __expf(m1 - mn1);
        float ls0 = 0.f, ls1 = 0.f;
        #pragma unroll
        for (int ni = 0; ni < 8; ni++) {
            float p0 = (sc[ni][0] == -INFINITY) ? 0.f : __expf(sc[ni][0] - mn0);
            float p1 = (sc[ni][1] == -INFINITY) ? 0.f : __expf(sc[ni][1] - mn0);
            float p2 = (sc[ni][2] == -INFINITY) ? 0.f : __expf(sc[ni][2] - mn1);
            float p3 = (sc[ni][3] == -INFINITY) ? 0.f : __expf(sc[ni][3] - mn1);
            sc[ni][0] = p0; sc[ni][1] = p1; sc[ni][2] = p2; sc[ni][3] = p3;
            ls0 += p0 + p1; ls1 += p2 + p3;
        }
        ls0 += __shfl_xor_sync(0xffffffffu, ls0, 1);
        ls0 += __shfl_xor_sync(0xffffffffu, ls0, 2);
        ls1 += __shfl_xor_sync(0xffffffffu, ls1, 1);
        ls1 += __shfl_xor_sync(0xffffffffu, ls1, 2);
        l0 = l0 * c0 + ls0;
        l1 = l1 * c1 + ls1;
        #pragma unroll
        for (int ni = 0; ni < 4; ni++) {
            oc[ni][0] *= c0; oc[ni][1] *= c0;
            oc[ni][2] *= c1; oc[ni][3] *= c1;
        }
        m0 = mn0; m1 = mn1;

        // P·V: C-fragments of S pack directly into A-fragments
        #pragma unroll
        for (int ks = 0; ks < 4; ks++) {
            uint32_t pa[4];
            __nv_bfloat162 t0 = __floats2bfloat162_rn(sc[2*ks][0], sc[2*ks][1]);
            __nv_bfloat162 t1 = __floats2bfloat162_rn(sc[2*ks][2], sc[2*ks][3]);
            __nv_bfloat162 t2 = __floats2bfloat162_rn(sc[2*ks+1][0], sc[2*ks+1][1]);
            __nv_bfloat162 t3 = __floats2bfloat162_rn(sc[2*ks+1][2], sc[2*ks+1][3]);
            pa[0] = *(uint32_t*)&t0; pa[1] = *(uint32_t*)&t1;
            pa[2] = *(uint32_t*)&t2; pa[3] = *(uint32_t*)&t3;
            #pragma unroll
            for (int ni = 0; ni < 4; ni++) {
                uint32_t vb[2];
                int off = ((ks * 16 + ll) * ASTR + ni * 8) * 2;
                LDMATRIX_X2_TRANS(vb[0], vb[1], uV + off);
                MMA_BF16(oc[ni], pa, vb);
            }
        }
    }

    float inv0 = (l0 > 0.f) ? 1.f / l0 : 0.f;
    float inv1 = (l1 > 0.f) ? 1.f / l1 : 0.f;
    float* op0 = outp + ((size_t)(b * NN + grow)) * DM + h * HDIM;
    float* op1 = op0 + 8 * DM;
    #pragma unroll
    for (int ni = 0; ni < 4; ni++) {
        int col = ni * 8 + qd * 2;
        *(float2*)(op0 + col) = make_float2(oc[ni][0] * inv0, oc[ni][1] * inv0);
        *(float2*)(op1 + col) = make_float2(oc[ni][2] * inv1, oc[ni][3] * inv1);
    }
}

// ---------------- residual + LayerNorm -------------------------------------
__global__ void add_ln_kernel(const float* __restrict__ xin, const float* __restrict__ res,
                              const float* __restrict__ g, const float* __restrict__ bb,
                              float* __restrict__ xout) {
    __shared__ float red[32];
    int row = blockIdx.x, tid = threadIdx.x;
    float v = xin[(size_t)row * DM + tid] + res[(size_t)row * DM + tid];
    float mu = blockReduceSum(v, red) * (1.0f / DM);
    float c = v - mu;
    float var = blockReduceSum(c * c, red) * (1.0f / DM);
    xout[(size_t)row * DM + tid] = c * rsqrtf(var + 1e-5f) * g[tid] + bb[tid];
}

// ---------------- pooling + MLP head ---------------------------------------
__global__ void head_kernel(const float* __restrict__ x,
                            const int* __restrict__ tmask, const int* __restrict__ imask,
                            const int* __restrict__ gidx,
                            const float* __restrict__ Wm1, const float* __restrict__ bm1,
                            const float* __restrict__ Wm2, const float* __restrict__ bm2,
                            const float* __restrict__ Wm3, const float* __restrict__ bm3,
                            float* __restrict__ out) {
    __shared__ float red[32];
    __shared__ float comb[769];
    __shared__ float h1[512];
    __shared__ float h2[256];
    int b = blockIdx.x, tid = threadIdx.x;

    float tcp = 0.f, icp = 0.f;
    for (int n = tid; n < NN; n += 256) {
        tcp += (tmask[b * NN + n] != 0) ? 1.f : 0.f;
        icp += (imask[b * NN + n] != 0) ? 1.f : 0.f;
    }
    float tc = fmaxf(blockReduceSum(tcp, red), 1.f);
    float ic = fmaxf(blockReduceSum(icp, red), 1.f);

    int d = tid;
    float tp = 0.f, ip = 0.f;
    for (int n = 0; n < NN; n++) {
        float v = x[((size_t)(b * NN + n)) * DM + d];
        if (tmask[b * NN + n] != 0) tp += v;
        if (imask[b * NN + n] != 0) ip += v;
    }
    tp /= tc; ip /= ic;
    int gi = gidx[b];
    float ge = x[((size_t)(b * NN + gi)) * DM + d];

    float n1s = blockReduceSum(tp * tp, red);
    float n2s = blockReduceSum(ip * ip, red);
    float dt  = blockReduceSum(tp * ip, red);
    float n1 = fmaxf(sqrtf(n1s), 1e-6f), n2 = fmaxf(sqrtf(n2s), 1e-6f);
    float conflict = 1.f - dt / (n1 * n2);

    comb[d] = ge; comb[256 + d] = tp; comb[512 + d] = ip;
    if (tid == 0) comb[768] = conflict;
    __syncthreads();

    for (int j = tid; j < 512; j += 256) {
        float a = bm1[j];
        for (int i = 0; i < 769; i++) a += comb[i] * Wm1[(size_t)i * 512 + j];
        h1[j] = geluf(a);
    }
    __syncthreads();
    {
        float a = bm2[tid];
        for (int i = 0; i < 512; i++) a += h1[i] * Wm2[(size_t)i * 256 + tid];
        h2[tid] = geluf(a);
    }
    __syncthreads();
    float tot = blockReduceSum(h2[tid] * Wm3[tid], red);
    if (tid == 0) out[b] = tot + bm3[0];
}

// ---------------- launch ----------------------------------------------------
extern "C" void kernel_launch(void* const* d_in, const int* in_sizes, int n_in,
                              void* d_out, int out_size) {
    const float* node_feats = (const float*)d_in[0];
    const int*   node_mask  = (const int*)d_in[1];
    const int*   text_mask  = (const int*)d_in[2];
    const int*   image_mask = (const int*)d_in[3];
    const int*   gidx       = (const int*)d_in[4];
    const int*   edge_index = (const int*)d_in[5];
    const int*   edge_type  = (const int*)d_in[6];
    const float* edge_weight= (const float*)d_in[7];
    const float* W_in  = (const float*)d_in[8];
    const float* b_in  = (const float*)d_in[9];
    const float* Wqkv  = (const float*)d_in[10];
    const float* bqkv  = (const float*)d_in[11];
    const float* Wo    = (const float*)d_in[12];
    const float* bo    = (const float*)d_in[13];
    const float* ln1_g = (const float*)d_in[14];
    const float* ln1_b = (const float*)d_in[15];
    const float* ln2_g = (const float*)d_in[16];
    const float* ln2_b = (const float*)d_in[17];
    const float* Wff1  = (const float*)d_in[18];
    const float* bff1  = (const float*)d_in[19];
    const float* Wff2  = (const float*)d_in[20];
    const float* bff2  = (const float*)d_in[21];
    const float* et_emb= (const float*)d_in[22];
    const float* Wm1   = (const float*)d_in[23];
    const float* bm1   = (const float*)d_in[24];
    const float* Wm2   = (const float*)d_in[25];
    const float* bm2   = (const float*)d_in[26];
    const float* Wm3   = (const float*)d_in[27];
    const float* bm3   = (const float*)d_in[28];

    float *bias, *x, *qkv, *attn, *tmp, *ff;
    __nv_bfloat16 *wth, *wtl;
    cudaGetSymbolAddress((void**)&bias, g_bias);
    cudaGetSymbolAddress((void**)&x,    g_x);
    cudaGetSymbolAddress((void**)&qkv,  g_qkv);
    cudaGetSymbolAddress((void**)&attn, g_attn);
    cudaGetSymbolAddress((void**)&tmp,  g_tmp);
    cudaGetSymbolAddress((void**)&ff,   g_ff);
    cudaGetSymbolAddress((void**)&wth,  g_wt_hi);
    cudaGetSymbolAddress((void**)&wtl,  g_wt_lo);

    // ---- weight transpose + split (W[K,N] -> hi/lo[N,K]); layers batched ----
    split_kernel<<<dim3(DM / 32, IND / 32, 1), dim3(32, 8)>>>(
        W_in, wth + WT_IN_OFF, wtl + WT_IN_OFF, IND, DM, 0, 0);
    split_kernel<<<dim3(3 * DM / 32, DM / 32, NL), dim3(32, 8)>>>(
        Wqkv, wth + WT_LAYER(0) + WT_QKV_OFF, wtl + WT_LAYER(0) + WT_QKV_OFF,
        DM, 3 * DM, (size_t)DM * 3 * DM, 786432);
    split_kernel<<<dim3(DM / 32, DM / 32, NL), dim3(32, 8)>>>(
        Wo, wth + WT_LAYER(0) + WT_WO_OFF, wtl + WT_LAYER(0) + WT_WO_OFF,
        DM, DM, (size_t)DM * DM, 786432);
    split_kernel<<<dim3(FFD / 32, DM / 32, NL), dim3(32, 8)>>>(
        Wff1, wth + WT_LAYER(0) + WT_FF1_OFF, wtl + WT_LAYER(0) + WT_FF1_OFF,
        DM, FFD, (size_t)DM * FFD, 786432);
    split_kernel<<<dim3(DM / 32, FFD / 32, NL), dim3(32, 8)>>>(
        Wff2, wth + WT_LAYER(0) + WT_FF2_OFF, wtl + WT_LAYER(0) + WT_FF2_OFF,
        FFD, DM, (size_t)FFD * DM, 786432);

    size_t bias_elems = (size_t)NB * NH * NN * NN;
    zero_kernel<<<4096, 256>>>((float4*)bias, bias_elems / 4);
    scatter_kernel<<<(NB * NE + 255) / 256, 256>>>(edge_index, edge_type, edge_weight, et_emb, bias);

    // input projection
    mma_gemm_kernel<0><<<dim3(DM / 64, ROWS / 128), 256>>>(
        node_feats, wth + WT_IN_OFF, wtl + WT_IN_OFF, b_in, x, IND, DM);

    for (int l = 0; l < NL; l++) {
        size_t lo = WT_LAYER(l);
        mma_gemm_kernel<0><<<dim3(3 * DM / 64, ROWS / 128), 256>>>(
            x, wth + lo + WT_QKV_OFF, wtl + lo + WT_QKV_OFF, bqkv + (size_t)l * 3 * DM, qkv, DM, 3 * DM);
        attn_mma_kernel<<<dim3(NN / 64, NB * NH), 128>>>(qkv, bias, node_mask, attn);
        mma_gemm_kernel<0><<<dim3(DM / 64, ROWS / 128), 256>>>(
            attn, wth + lo + WT_WO_OFF, wtl + lo + WT_WO_OFF, bo + (size_t)l * DM, tmp, DM, DM);
        add_ln_kernel<<<ROWS, 256>>>(x, tmp, ln1_g + (size_t)l * DM, ln1_b + (size_t)l * DM, x);
        mma_gemm_kernel<1><<<dim3(FFD / 64, ROWS / 128), 256>>>(
            x, wth + lo + WT_FF1_OFF, wtl + lo + WT_FF1_OFF, bff1 + (size_t)l * FFD, ff, DM, FFD);
        mma_gemm_kernel<0><<<dim3(DM / 64, ROWS / 128), 256>>>(
            ff, wth + lo + WT_FF2_OFF, wtl + lo + WT_FF2_OFF, bff2 + (size_t)l * DM, tmp, FFD, DM);
        add_ln_kernel<<<ROWS, 256>>>(x, tmp, ln2_g + (size_t)l * DM, ln2_b + (size_t)l * DM, x);
    }

    head_kernel<<<NB, 256>>>(x, text_mask, image_mask, gidx,
                             Wm1, bm1, Wm2, bm2, Wm3, bm3, (float*)d_out);
}

// round 16
// speedup vs baseline: 3.1596x; 1.0789x over previous
#include <cuda_runtime.h>
#include <cuda_bf16.h>
#include <math.h>
#include <stdint.h>

#define NB   16
#define NN   512
#define DM   256
#define NH   8
#define HDIM 32
#define NL   3
#define NE   4096
#define IND  768
#define FFD  1024
#define ROWS (NB*NN)   // 8192

// ---------------- scratch (device globals; no allocation allowed) ----------
__device__ float g_bias[(size_t)NB*NH*NN*NN];   // 134 MB attn bias (B,H,N,N)
__device__ float g_x   [(size_t)ROWS*DM];
__device__ float g_qkv [(size_t)ROWS*3*DM];
__device__ float g_attn[(size_t)ROWS*DM];
__device__ float g_tmp [(size_t)ROWS*DM];
__device__ float g_ff  [(size_t)ROWS*FFD];
// transposed + split weights, [N][K] layout, bf16 hi/lo
#define WT_IN_OFF   0
#define WT_LAYER(l) (196608 + (size_t)(l) * 786432)
#define WT_QKV_OFF  0
#define WT_WO_OFF   196608
#define WT_FF1_OFF  (196608 + 65536)
#define WT_FF2_OFF  (196608 + 65536 + 262144)
__device__ __nv_bfloat16 g_wt_hi[2555904];
__device__ __nv_bfloat16 g_wt_lo[2555904];

// ---------------- helpers --------------------------------------------------
__device__ __forceinline__ uint32_t smem_u32(const void* p) {
    uint32_t a;
    asm("{ .reg .u64 t; cvta.to.shared.u64 t, %1; cvt.u32.u64 %0, t; }" : "=r"(a) : "l"(p));
    return a;
}
__device__ __forceinline__ float geluf(float v) {
    return 0.5f * v * (1.0f + erff(v * 0.7071067811865476f));
}
__device__ __forceinline__ float blockReduceSum(float v, float* sh) {
    int lane = threadIdx.x & 31, w = threadIdx.x >> 5;
    #pragma unroll
    for (int o = 16; o > 0; o >>= 1) v += __shfl_down_sync(0xffffffffu, v, o);
    __syncthreads();
    if (lane == 0) sh[w] = v;
    __syncthreads();
    if (w == 0) {
        int nw = blockDim.x >> 5;
        float t = (lane < nw) ? sh[lane] : 0.0f;
        #pragma unroll
        for (int o = 16; o > 0; o >>= 1) t += __shfl_down_sync(0xffffffffu, t, o);
        if (lane == 0) sh[0] = t;
    }
    __syncthreads();
    return sh[0];
}

#define LDMATRIX_X4(r0, r1, r2, r3, a) \
    asm volatile("ldmatrix.sync.aligned.m8n8.x4.shared.b16 {%0,%1,%2,%3}, [%4];" \
                 : "=r"(r0), "=r"(r1), "=r"(r2), "=r"(r3) : "r"(a))
#define LDMATRIX_X2(r0, r1, a) \
    asm volatile("ldmatrix.sync.aligned.m8n8.x2.shared.b16 {%0,%1}, [%2];" \
                 : "=r"(r0), "=r"(r1) : "r"(a))
#define LDMATRIX_X2_TRANS(r0, r1, a) \
    asm volatile("ldmatrix.sync.aligned.m8n8.x2.trans.shared.b16 {%0,%1}, [%2];" \
                 : "=r"(r0), "=r"(r1) : "r"(a))
#define MMA_BF16(c, a, b) \
    asm volatile("mma.sync.aligned.m16n8k16.row.col.f32.bf16.bf16.f32 " \
                 "{%0,%1,%2,%3}, {%4,%5,%6,%7}, {%8,%9}, {%0,%1,%2,%3};" \
                 : "+f"((c)[0]), "+f"((c)[1]), "+f"((c)[2]), "+f"((c)[3]) \
                 : "r"((a)[0]), "r"((a)[1]), "r"((a)[2]), "r"((a)[3]), \
                   "r"((b)[0]), "r"((b)[1]))

// ---------------- bias build ------------------------------------------------
__global__ void zero_kernel(float4* p, size_t n4) {
    size_t stride = (size_t)gridDim.x * blockDim.x;
    for (size_t i = (size_t)blockIdx.x * blockDim.x + threadIdx.x; i < n4; i += stride)
        p[i] = make_float4(0.f, 0.f, 0.f, 0.f);
}
__global__ void scatter_kernel(const int* __restrict__ edge_index,
                               const int* __restrict__ edge_type,
                               const float* __restrict__ edge_weight,
                               const float* __restrict__ et_emb,
                               float* __restrict__ bias) {
    int t = blockIdx.x * blockDim.x + threadIdx.x;
    if (t >= NB * NE) return;
    int b = t / NE, e = t % NE;
    int src = edge_index[(size_t)b * 2 * NE + e];
    int dst = edge_index[(size_t)b * 2 * NE + NE + e];
    int et  = edge_type[(size_t)b * NE + e];
    float w = edge_weight[(size_t)b * NE + e];
    float add = (et == 2) ? w : 0.0f;
    size_t base = (size_t)b * NH * NN * NN + (size_t)src * NN + dst;
    #pragma unroll
    for (int h = 0; h < NH; h++)
        atomicAdd(&bias[base + (size_t)h * NN * NN], et_emb[et * NH + h] + add);
}

// --------- weight transpose + bf16 split (batched over layers via grid.z) ---
__global__ void split_kernel(const float* __restrict__ W,
                             __nv_bfloat16* __restrict__ hi, __nv_bfloat16* __restrict__ lo,
                             int K, int Nc, size_t wStride, size_t tStride) {
    __shared__ float t[32][33];
    int layer = blockIdx.z;
    W  += (size_t)layer * wStride;
    hi += (size_t)layer * tStride;
    lo += (size_t)layer * tStride;
    int n0 = blockIdx.x * 32, k0 = blockIdx.y * 32;
    int x = threadIdx.x, y = threadIdx.y;   // 32 x 8
    #pragma unroll
    for (int i = y; i < 32; i += 8) t[i][x] = W[(size_t)(k0 + i) * Nc + n0 + x];
    __syncthreads();
    #pragma unroll
    for (int i = y; i < 32; i += 8) {
        float v = t[x][i];
        __nv_bfloat16 h = __float2bfloat16_rn(v);
        float l = v - __bfloat162float(h);
        size_t o = (size_t)(n0 + i) * K + k0 + x;
        hi[o] = h;
        lo[o] = __float2bfloat16_rn(l);
    }
}

// ---------------- split-bf16 mma.sync GEMM ----------------------------------
// C[M,Nc] = act(A[M,K] @ Wt[Nc,K]^T + bias), fp32-accurate via hi/lo split.
// Block tile 128x128, K-chunk 32, 256 threads (8 warps 4x2), warp tile 32x64.
// Next chunk's global loads are register-prefetched during current compute.
#define ASTR 40   // bf16 row stride in smem (80B, conflict-free for ldmatrix)
template <int ACT>
__global__ void mma_gemm_kernel(const float* __restrict__ A,
                                const __nv_bfloat16* __restrict__ Whi,
                                const __nv_bfloat16* __restrict__ Wlo,
                                const float* __restrict__ bias, float* __restrict__ C,
                                int K, int Nc) {
    __shared__ __nv_bfloat16 sAh[128 * ASTR], sAl[128 * ASTR];
    __shared__ __nv_bfloat16 sBh[128 * ASTR], sBl[128 * ASTR];
    int tid = threadIdx.x;
    int warp = tid >> 5, lane = tid & 31;
    int wm = warp & 3, wn = warp >> 2;          // warp tile (wm*32, wn*64)
    int bm = blockIdx.y * 128, bn = blockIdx.x * 128;

    float acc[2][8][4];
    #pragma unroll
    for (int i = 0; i < 2; i++)
        #pragma unroll
        for (int j = 0; j < 8; j++)
            #pragma unroll
            for (int q = 0; q < 4; q++) acc[i][j][q] = 0.f;

    // fill pointers: A 128 rows x 32 floats; B 128 rows x 32 bf16 (hi+lo)
    int arow = tid >> 1, ahalf = tid & 1;
    const float* ap = A + (size_t)(bm + arow) * K + ahalf * 16;
    const __nv_bfloat16* bph = Whi + (size_t)(bn + arow) * K + ahalf * 16;
    const __nv_bfloat16* bpl = Wlo + (size_t)(bn + arow) * K + ahalf * 16;

    uint32_t uAh = smem_u32(sAh), uAl = smem_u32(sAl);
    uint32_t uBh = smem_u32(sBh), uBl = smem_u32(sBl);

    // ldmatrix per-lane address components (element offsets within tile)
    int a_r = (lane & 7) + ((lane >> 3) & 1) * 8;   // row within 16
    int a_c = (lane >> 4) * 8;                      // k-col within 16
    int ll = lane & 15;
    int b_r = ll & 7;                               // row within 8
    int b_c = (ll >> 3) * 8;                        // k-col within 16

    int nchunks = K >> 5;

    // register prefetch buffers
    float4 aR[4];
    uint4 bRh[2], bRl[2];
    #pragma unroll
    for (int j = 0; j < 4; j++) aR[j] = *(const float4*)(ap + j * 4);
    bRh[0] = *(const uint4*)bph;       bRh[1] = *(const uint4*)(bph + 8);
    bRl[0] = *(const uint4*)bpl;       bRl[1] = *(const uint4*)(bpl + 8);

    for (int c = 0; c < nchunks; c++) {
        // ---- store prefetched regs -> smem (split A on the fly) ----
        #pragma unroll
        for (int j = 0; j < 4; j++) {
            float4 v = aR[j];
            __nv_bfloat162 h0 = __floats2bfloat162_rn(v.x, v.y);
            __nv_bfloat162 h1 = __floats2bfloat162_rn(v.z, v.w);
            __nv_bfloat162 l0 = __floats2bfloat162_rn(v.x - __low2float(h0), v.y - __high2float(h0));
            __nv_bfloat162 l1 = __floats2bfloat162_rn(v.z - __low2float(h1), v.w - __high2float(h1));
            int e = arow * ASTR + ahalf * 16 + j * 4;
            *(__nv_bfloat162*)(sAh + e) = h0; *(__nv_bfloat162*)(sAh + e + 2) = h1;
            *(__nv_bfloat162*)(sAl + e) = l0; *(__nv_bfloat162*)(sAl + e + 2) = l1;
        }
        {
            int e = arow * ASTR + ahalf * 16;
            *(uint4*)(sBh + e) = bRh[0]; *(uint4*)(sBh + e + 8) = bRh[1];
            *(uint4*)(sBl + e) = bRl[0]; *(uint4*)(sBl + e + 8) = bRl[1];
        }
        __syncthreads();

        // ---- issue next chunk's global loads (latency hidden by compute) ----
        if (c + 1 < nchunks) {
            int k1 = (c + 1) << 5;
            #pragma unroll
            for (int j = 0; j < 4; j++) aR[j] = *(const float4*)(ap + k1 + j * 4);
            bRh[0] = *(const uint4*)(bph + k1); bRh[1] = *(const uint4*)(bph + k1 + 8);
            bRl[0] = *(const uint4*)(bpl + k1); bRl[1] = *(const uint4*)(bpl + k1 + 8);
        }

        // ---- compute current chunk ----
        #pragma unroll
        for (int s = 0; s < 32; s += 16) {
            uint32_t ah[2][4], al[2][4];
            #pragma unroll
            for (int mi = 0; mi < 2; mi++) {
                int off = ((wm * 32 + mi * 16 + a_r) * ASTR + s + a_c) * 2;
                LDMATRIX_X4(ah[mi][0], ah[mi][1], ah[mi][2], ah[mi][3], uAh + off);
                LDMATRIX_X4(al[mi][0], al[mi][1], al[mi][2], al[mi][3], uAl + off);
            }
            #pragma unroll
            for (int ni = 0; ni < 8; ni++) {
                uint32_t bh[2], bl[2];
                int off = ((wn * 64 + ni * 8 + b_r) * ASTR + s + b_c) * 2;
                LDMATRIX_X2(bh[0], bh[1], uBh + off);
                LDMATRIX_X2(bl[0], bl[1], uBl + off);
                #pragma unroll
                for (int mi = 0; mi < 2; mi++) {
                    MMA_BF16(acc[mi][ni], ah[mi], bh);
                    MMA_BF16(acc[mi][ni], ah[mi], bl);
                    MMA_BF16(acc[mi][ni], al[mi], bh);
                }
            }
        }
        __syncthreads();
    }

    // ---- epilogue ----
    int gid = lane >> 2, tid2 = (lane & 3) * 2;
    #pragma unroll
    for (int mi = 0; mi < 2; mi++) {
        #pragma unroll
        for (int ni = 0; ni < 8; ni++) {
            int row = bm + wm * 32 + mi * 16 + gid;
            int col = bn + wn * 64 + ni * 8 + tid2;
            float b0 = bias[col], b1 = bias[col + 1];
            float v0 = acc[mi][ni][0] + b0, v1 = acc[mi][ni][1] + b1;
            float v2 = acc[mi][ni][2] + b0, v3 = acc[mi][ni][3] + b1;
            if (ACT == 1) { v0 = geluf(v0); v1 = geluf(v1); v2 = geluf(v2); v3 = geluf(v3); }
            *(float2*)&C[(size_t)row * Nc + col] = make_float2(v0, v1);
            *(float2*)&C[(size_t)(row + 8) * Nc + col] = make_float2(v2, v3);
        }
    }
}

// ---------------- attention (flash-style, tensor-core) ----------------------
// Block = (b,h, 64-row q-tile). 128 threads, 4 warps, warp = 16 q-rows.
// S = QK^T via split-bf16 (3 MMAs); P·V in plain bf16; V via ldmatrix.trans.
__global__ void attn_mma_kernel(const float* __restrict__ qkv,
                                const float* __restrict__ bias,
                                const int* __restrict__ node_mask,
                                float* __restrict__ outp) {
    __shared__ __nv_bfloat16 sQh[64 * ASTR], sQl[64 * ASTR];
    __shared__ __nv_bfloat16 sKh[64 * ASTR], sKl[64 * ASTR];
    __shared__ __nv_bfloat16 sV [64 * ASTR];
    __shared__ float maskb[64];

    int bh = blockIdx.y, b = bh >> 3, h = bh & 7;
    int i0 = blockIdx.x * 64;
    int tid = threadIdx.x, warp = tid >> 5, lane = tid & 31;
    int gid = lane >> 2, qd = lane & 3, ll = lane & 15;
    const float scale = 0.17677669529663687f;   // 1/sqrt(32)

    // load Q (64 x 32) with hi/lo split
    {
        int row = tid >> 1, halfq = tid & 1;
        const float* qp = qkv + ((size_t)(b * NN + i0 + row)) * (3 * DM) + h * HDIM + halfq * 16;
        #pragma unroll
        for (int j = 0; j < 4; j++) {
            float4 v = *(const float4*)(qp + j * 4);
            __nv_bfloat162 h0 = __floats2bfloat162_rn(v.x, v.y);
            __nv_bfloat162 h1 = __floats2bfloat162_rn(v.z, v.w);
            __nv_bfloat162 l0 = __floats2bfloat162_rn(v.x - __low2float(h0), v.y - __high2float(h0));
            __nv_bfloat162 l1 = __floats2bfloat162_rn(v.z - __low2float(h1), v.w - __high2float(h1));
            int e = row * ASTR + halfq * 16 + j * 4;
            *(__nv_bfloat162*)(sQh + e) = h0; *(__nv_bfloat162*)(sQh + e + 2) = h1;
            *(__nv_bfloat162*)(sQl + e) = l0; *(__nv_bfloat162*)(sQl + e + 2) = l1;
        }
    }

    float m0 = -INFINITY, m1 = -INFINITY, l0 = 0.f, l1 = 0.f;
    float oc[4][4];
    #pragma unroll
    for (int i = 0; i < 4; i++)
        #pragma unroll
        for (int j = 0; j < 4; j++) oc[i][j] = 0.f;

    int a_r = (lane & 7) + ((lane >> 3) & 1) * 8;
    int a_c = (lane >> 4) * 8;
    int b_r = ll & 7, b_c = (ll >> 3) * 8;

    uint32_t uQh = smem_u32(sQh), uQl = smem_u32(sQl);
    uint32_t uKh = smem_u32(sKh), uKl = smem_u32(sKl), uV = smem_u32(sV);

    int grow = i0 + warp * 16 + gid;
    const float* brow0 = bias + ((size_t)bh * NN + grow) * NN;
    const float* brow1 = brow0 + 8 * NN;

    for (int j0 = 0; j0 < NN; j0 += 64) {
        __syncthreads();
        // load K (split) + V (plain) chunk
        {
            int row = tid >> 1, halfq = tid & 1;
            const float* kp = qkv + ((size_t)(b * NN + j0 + row)) * (3 * DM) + DM + h * HDIM + halfq * 16;
            const float* vp = kp + DM;
            #pragma unroll
            for (int j = 0; j < 4; j++) {
                float4 v = *(const float4*)(kp + j * 4);
                __nv_bfloat162 h0 = __floats2bfloat162_rn(v.x, v.y);
                __nv_bfloat162 h1 = __floats2bfloat162_rn(v.z, v.w);
                __nv_bfloat162 l0 = __floats2bfloat162_rn(v.x - __low2float(h0), v.y - __high2float(h0));
                __nv_bfloat162 l1 = __floats2bfloat162_rn(v.z - __low2float(h1), v.w - __high2float(h1));
                int e = row * ASTR + halfq * 16 + j * 4;
                *(__nv_bfloat162*)(sKh + e) = h0; *(__nv_bfloat162*)(sKh + e + 2) = h1;
                *(__nv_bfloat162*)(sKl + e) = l0; *(__nv_bfloat162*)(sKl + e + 2) = l1;
                float4 vv = *(const float4*)(vp + j * 4);
                *(__nv_bfloat162*)(sV + e)     = __floats2bfloat162_rn(vv.x, vv.y);
                *(__nv_bfloat162*)(sV + e + 2) = __floats2bfloat162_rn(vv.z, vv.w);
            }
        }
        if (tid < 64) maskb[tid] = node_mask[b * NN + j0 + tid] ? 0.f : -INFINITY;
        __syncthreads();

        // Q fragments (2 k-steps)
        uint32_t qh[2][4], ql[2][4];
        #pragma unroll
        for (int s = 0; s < 2; s++) {
            int off = ((warp * 16 + a_r) * ASTR + s * 16 + a_c) * 2;
            LDMATRIX_X4(qh[s][0], qh[s][1], qh[s][2], qh[s][3], uQh + off);
            LDMATRIX_X4(ql[s][0], ql[s][1], ql[s][2], ql[s][3], uQl + off);
        }
        // S = QK^T (split, 3 MMAs per k-step)
        float sc[8][4];
        #pragma unroll
        for (int ni = 0; ni < 8; ni++) {
            sc[ni][0] = sc[ni][1] = sc[ni][2] = sc[ni][3] = 0.f;
            #pragma unroll
            for (int s = 0; s < 2; s++) {
                uint32_t kh[2], kl[2];
                int off = ((ni * 8 + b_r) * ASTR + s * 16 + b_c) * 2;
                LDMATRIX_X2(kh[0], kh[1], uKh + off);
                LDMATRIX_X2(kl[0], kl[1], uKl + off);
                MMA_BF16(sc[ni], qh[s], kh);
                MMA_BF16(sc[ni], qh[s], kl);
                MMA_BF16(sc[ni], ql[s], kh);
            }
        }
        // scale + bias + mask, row maxes
        float mx0 = -INFINITY, mx1 = -INFINITY;
        #pragma unroll
        for (int ni = 0; ni < 8; ni++) {
            int col = ni * 8 + qd * 2;
            float2 bv0 = *(const float2*)(brow0 + j0 + col);
            float2 bv1 = *(const float2*)(brow1 + j0 + col);
            sc[ni][0] = sc[ni][0] * scale + bv0.x + maskb[col];
            sc[ni][1] = sc[ni][1] * scale + bv0.y + maskb[col + 1];
            sc[ni][2] = sc[ni][2] * scale + bv1.x + maskb[col];
            sc[ni][3] = sc[ni][3] * scale + bv1.y + maskb[col + 1];
            mx0 = fmaxf(mx0, fmaxf(sc[ni][0], sc[ni][1]));
            mx1 = fmaxf(mx1, fmaxf(sc[ni][2], sc[ni][3]));
        }
        mx0 = fmaxf(mx0, __shfl_xor_sync(0xffffffffu, mx0, 1));
        mx0 = fmaxf(mx0, __shfl_xor_sync(0xffffffffu, mx0, 2));
        mx1 = fmaxf(mx1, __shfl_xor_sync(0xffffffffu, mx1, 1));
        mx1 = fmaxf(mx1, __shfl_xor_sync(0xffffffffu, mx1, 2));

        float mn0 = fmaxf(m0, mx0), mn1 = fmaxf(m1, mx1);
        float c0 = (mn0 == -INFINITY) ? 1.f : __expf(m0 - mn0);
        float c1 = (mn1 == -INFINITY) ? 1.f : __expf(m1 - mn1);
        float ls0 = 0.f, ls1 = 0.f;
        #pragma unroll
        for (int ni = 0; ni < 8; ni++) {
            float p0 = (sc[ni][0] == -INFINITY) ? 0.f : __expf(sc[ni][0] - mn0);
            float p1 = (sc[ni][1] == -INFINITY) ? 0.f : __expf(sc[ni][1] - mn0);
            float p2 = (sc[ni][2] == -INFINITY) ? 0.f : __expf(sc[ni][2] - mn1);
            float p3 = (sc[ni][3] == -INFINITY) ? 0.f : __expf(sc[ni][3] - mn1);
            sc[ni][0] = p0; sc[ni][1] = p1; sc[ni][2] = p2; sc[ni][3] = p3;
            ls0 += p0 + p1; ls1 += p2 + p3;
        }
        ls0 += __shfl_xor_sync(0xffffffffu, ls0, 1);
        ls0 += __shfl_xor_sync(0xffffffffu, ls0, 2);
        ls1 += __shfl_xor_sync(0xffffffffu, ls1, 1);
        ls1 += __shfl_xor_sync(0xffffffffu, ls1, 2);
        l0 = l0 * c0 + ls0;
        l1 = l1 * c1 + ls1;
        #pragma unroll
        for (int ni = 0; ni < 4; ni++) {
            oc[ni][0] *= c0; oc[ni][1] *= c0;
            oc[ni][2] *= c1; oc[ni][3] *= c1;
        }
        m0 = mn0; m1 = mn1;

        // P·V: C-fragments of S pack directly into A-fragments
        #pragma unroll
        for (int ks = 0; ks < 4; ks++) {
            uint32_t pa[4];
            __nv_bfloat162 t0 = __floats2bfloat162_rn(sc[2*ks][0], sc[2*ks][1]);
            __nv_bfloat162 t1 = __floats2bfloat162_rn(sc[2*ks][2], sc[2*ks][3]);
            __nv_bfloat162 t2 = __floats2bfloat162_rn(sc[2*ks+1][0], sc[2*ks+1][1]);
            __nv_bfloat162 t3 = __floats2bfloat162_rn(sc[2*ks+1][2], sc[2*ks+1][3]);
            pa[0] = *(uint32_t*)&t0; pa[1] = *(uint32_t*)&t1;
            pa[2] = *(uint32_t*)&t2; pa[3] = *(uint32_t*)&t3;
            #pragma unroll
            for (int ni = 0; ni < 4; ni++) {
                uint32_t vb[2];
                int off = ((ks * 16 + ll) * ASTR + ni * 8) * 2;
                LDMATRIX_X2_TRANS(vb[0], vb[1], uV + off);
                MMA_BF16(oc[ni], pa, vb);
            }
        }
    }

    float inv0 = (l0 > 0.f) ? 1.f / l0 : 0.f;
    float inv1 = (l1 > 0.f) ? 1.f / l1 : 0.f;
    float* op0 = outp + ((size_t)(b * NN + grow)) * DM + h * HDIM;
    float* op1 = op0 + 8 * DM;
    #pragma unroll
    for (int ni = 0; ni < 4; ni++) {
        int col = ni * 8 + qd * 2;
        *(float2*)(op0 + col) = make_float2(oc[ni][0] * inv0, oc[ni][1] * inv0);
        *(float2*)(op1 + col) = make_float2(oc[ni][2] * inv1, oc[ni][3] * inv1);
    }
}

// ---------------- residual + LayerNorm (warp per row, shuffle-only) ---------
__global__ void add_ln_kernel(const float* __restrict__ xin, const float* __restrict__ res,
                              const float* __restrict__ g, const float* __restrict__ bb,
                              float* __restrict__ xout) {
    int warp = threadIdx.x >> 5, lane = threadIdx.x & 31;
    int row = blockIdx.x * 8 + warp;
    const float4* xp = (const float4*)(xin + (size_t)row * DM);
    const float4* rp = (const float4*)(res + (size_t)row * DM);
    float4 a0 = xp[lane * 2], a1 = xp[lane * 2 + 1];
    float4 r0 = rp[lane * 2], r1 = rp[lane * 2 + 1];
    float v[8] = {a0.x + r0.x, a0.y + r0.y, a0.z + r0.z, a0.w + r0.w,
                  a1.x + r1.x, a1.y + r1.y, a1.z + r1.z, a1.w + r1.w};
    float s = 0.f;
    #pragma unroll
    for (int i = 0; i < 8; i++) s += v[i];
    #pragma unroll
    for (int o = 16; o > 0; o >>= 1) s += __shfl_xor_sync(0xffffffffu, s, o);
    float mu = s * (1.0f / DM);
    float q = 0.f;
    #pragma unroll
    for (int i = 0; i < 8; i++) { v[i] -= mu; q += v[i] * v[i]; }
    #pragma unroll
    for (int o = 16; o > 0; o >>= 1) q += __shfl_xor_sync(0xffffffffu, q, o);
    float rstd = rsqrtf(q * (1.0f / DM) + 1e-5f);
    const float4* gp = (const float4*)g;
    const float4* bp = (const float4*)bb;
    float4 g0 = gp[lane * 2], g1 = gp[lane * 2 + 1];
    float4 b0 = bp[lane * 2], b1 = bp[lane * 2 + 1];
    float4 o0, o1;
    o0.x = v[0] * rstd * g0.x + b0.x; o0.y = v[1] * rstd * g0.y + b0.y;
    o0.z = v[2] * rstd * g0.z + b0.z; o0.w = v[3] * rstd * g0.w + b0.w;
    o1.x = v[4] * rstd * g1.x + b1.x; o1.y = v[5] * rstd * g1.y + b1.y;
    o1.z = v[6] * rstd * g1.z + b1.z; o1.w = v[7] * rstd * g1.w + b1.w;
    float4* op = (float4*)(xout + (size_t)row * DM);
    op[lane * 2] = o0; op[lane * 2 + 1] = o1;
}

// ---------------- pooling + MLP head ---------------------------------------
__global__ void head_kernel(const float* __restrict__ x,
                            const int* __restrict__ tmask, const int* __restrict__ imask,
                            const int* __restrict__ gidx,
                            const float* __restrict__ Wm1, const float* __restrict__ bm1,
                            const float* __restrict__ Wm2, const float* __restrict__ bm2,
                            const float* __restrict__ Wm3, const float* __restrict__ bm3,
                            float* __restrict__ out) {
    __shared__ float red[32];
    __shared__ float comb[769];
    __shared__ float h1[512];
    __shared__ float h2[256];
    int b = blockIdx.x, tid = threadIdx.x;

    float tcp = 0.f, icp = 0.f;
    for (int n = tid; n < NN; n += 256) {
        tcp += (tmask[b * NN + n] != 0) ? 1.f : 0.f;
        icp += (imask[b * NN + n] != 0) ? 1.f : 0.f;
    }
    float tc = fmaxf(blockReduceSum(tcp, red), 1.f);
    float ic = fmaxf(blockReduceSum(icp, red), 1.f);

    int d = tid;
    float tp = 0.f, ip = 0.f;
    for (int n = 0; n < NN; n++) {
        float v = x[((size_t)(b * NN + n)) * DM + d];
        if (tmask[b * NN + n] != 0) tp += v;
        if (imask[b * NN + n] != 0) ip += v;
    }
    tp /= tc; ip /= ic;
    int gi = gidx[b];
    float ge = x[((size_t)(b * NN + gi)) * DM + d];

    float n1s = blockReduceSum(tp * tp, red);
    float n2s = blockReduceSum(ip * ip, red);
    float dt  = blockReduceSum(tp * ip, red);
    float n1 = fmaxf(sqrtf(n1s), 1e-6f), n2 = fmaxf(sqrtf(n2s), 1e-6f);
    float conflict = 1.f - dt / (n1 * n2);

    comb[d] = ge; comb[256 + d] = tp; comb[512 + d] = ip;
    if (tid == 0) comb[768] = conflict;
    __syncthreads();

    for (int j = tid; j < 512; j += 256) {
        float a = bm1[j];
        for (int i = 0; i < 769; i++) a += comb[i] * Wm1[(size_t)i * 512 + j];
        h1[j] = geluf(a);
    }
    __syncthreads();
    {
        float a = bm2[tid];
        for (int i = 0; i < 512; i++) a += h1[i] * Wm2[(size_t)i * 256 + tid];
        h2[tid] = geluf(a);
    }
    __syncthreads();
    float tot = blockReduceSum(h2[tid] * Wm3[tid], red);
    if (tid == 0) out[b] = tot + bm3[0];
}

// ---------------- launch ----------------------------------------------------
extern "C" void kernel_launch(void* const* d_in, const int* in_sizes, int n_in,
                              void* d_out, int out_size) {
    const float* node_feats = (const float*)d_in[0];
    const int*   node_mask  = (const int*)d_in[1];
    const int*   text_mask  = (const int*)d_in[2];
    const int*   image_mask = (const int*)d_in[3];
    const int*   gidx       = (const int*)d_in[4];
    const int*   edge_index = (const int*)d_in[5];
    const int*   edge_type  = (const int*)d_in[6];
    const float* edge_weight= (const float*)d_in[7];
    const float* W_in  = (const float*)d_in[8];
    const float* b_in  = (const float*)d_in[9];
    const float* Wqkv  = (const float*)d_in[10];
    const float* bqkv  = (const float*)d_in[11];
    const float* Wo    = (const float*)d_in[12];
    const float* bo    = (const float*)d_in[13];
    const float* ln1_g = (const float*)d_in[14];
    const float* ln1_b = (const float*)d_in[15];
    const float* ln2_g = (const float*)d_in[16];
    const float* ln2_b = (const float*)d_in[17];
    const float* Wff1  = (const float*)d_in[18];
    const float* bff1  = (const float*)d_in[19];
    const float* Wff2  = (const float*)d_in[20];
    const float* bff2  = (const float*)d_in[21];
    const float* et_emb= (const float*)d_in[22];
    const float* Wm1   = (const float*)d_in[23];
    const float* bm1   = (const float*)d_in[24];
    const float* Wm2   = (const float*)d_in[25];
    const float* bm2   = (const float*)d_in[26];
    const float* Wm3   = (const float*)d_in[27];
    const float* bm3   = (const float*)d_in[28];

    float *bias, *x, *qkv, *attn, *tmp, *ff;
    __nv_bfloat16 *wth, *wtl;
    cudaGetSymbolAddress((void**)&bias, g_bias);
    cudaGetSymbolAddress((void**)&x,    g_x);
    cudaGetSymbolAddress((void**)&qkv,  g_qkv);
    cudaGetSymbolAddress((void**)&attn, g_attn);
    cudaGetSymbolAddress((void**)&tmp,  g_tmp);
    cudaGetSymbolAddress((void**)&ff,   g_ff);
    cudaGetSymbolAddress((void**)&wth,  g_wt_hi);
    cudaGetSymbolAddress((void**)&wtl,  g_wt_lo);

    // ---- weight transpose + split (W[K,N] -> hi/lo[N,K]); layers batched ----
    split_kernel<<<dim3(DM / 32, IND / 32, 1), dim3(32, 8)>>>(
        W_in, wth + WT_IN_OFF, wtl + WT_IN_OFF, IND, DM, 0, 0);
    split_kernel<<<dim3(3 * DM / 32, DM / 32, NL), dim3(32, 8)>>>(
        Wqkv, wth + WT_LAYER(0) + WT_QKV_OFF, wtl + WT_LAYER(0) + WT_QKV_OFF,
        DM, 3 * DM, (size_t)DM * 3 * DM, 786432);
    split_kernel<<<dim3(DM / 32, DM / 32, NL), dim3(32, 8)>>>(
        Wo, wth + WT_LAYER(0) + WT_WO_OFF, wtl + WT_LAYER(0) + WT_WO_OFF,
        DM, DM, (size_t)DM * DM, 786432);
    split_kernel<<<dim3(FFD / 32, DM / 32, NL), dim3(32, 8)>>>(
        Wff1, wth + WT_LAYER(0) + WT_FF1_OFF, wtl + WT_LAYER(0) + WT_FF1_OFF,
        DM, FFD, (size_t)DM * FFD, 786432);
    split_kernel<<<dim3(DM / 32, FFD / 32, NL), dim3(32, 8)>>>(
        Wff2, wth + WT_LAYER(0) + WT_FF2_OFF, wtl + WT_LAYER(0) + WT_FF2_OFF,
        FFD, DM, (size_t)FFD * DM, 786432);

    size_t bias_elems = (size_t)NB * NH * NN * NN;
    zero_kernel<<<4096, 256>>>((float4*)bias, bias_elems / 4);
    scatter_kernel<<<(NB * NE + 255) / 256, 256>>>(edge_index, edge_type, edge_weight, et_emb, bias);

    // input projection
    mma_gemm_kernel<0><<<dim3(DM / 128, ROWS / 128), 256>>>(
        node_feats, wth + WT_IN_OFF, wtl + WT_IN_OFF, b_in, x, IND, DM);

    for (int l = 0; l < NL; l++) {
        size_t lo = WT_LAYER(l);
        mma_gemm_kernel<0><<<dim3(3 * DM / 128, ROWS / 128), 256>>>(
            x, wth + lo + WT_QKV_OFF, wtl + lo + WT_QKV_OFF, bqkv + (size_t)l * 3 * DM, qkv, DM, 3 * DM);
        attn_mma_kernel<<<dim3(NN / 64, NB * NH), 128>>>(qkv, bias, node_mask, attn);
        mma_gemm_kernel<0><<<dim3(DM / 128, ROWS / 128), 256>>>(
            attn, wth + lo + WT_WO_OFF, wtl + lo + WT_WO_OFF, bo + (size_t)l * DM, tmp, DM, DM);
        add_ln_kernel<<<ROWS / 8, 256>>>(x, tmp, ln1_g + (size_t)l * DM, ln1_b + (size_t)l * DM, x);
        mma_gemm_kernel<1><<<dim3(FFD / 128, ROWS / 128), 256>>>(
            x, wth + lo + WT_FF1_OFF, wtl + lo + WT_FF1_OFF, bff1 + (size_t)l * FFD, ff, DM, FFD);
        mma_gemm_kernel<0><<<dim3(DM / 128, ROWS / 128), 256>>>(
            ff, wth + lo + WT_FF2_OFF, wtl + lo + WT_FF2_OFF, bff2 + (size_t)l * DM, tmp, FFD, DM);
        add_ln_kernel<<<ROWS / 8, 256>>>(x, tmp, ln2_g + (size_t)l * DM, ln2_b + (size_t)l * DM, x);
    }

    head_kernel<<<NB, 256>>>(x, text_mask, image_mask, gidx,
                             Wm1, bm1, Wm2, bm2, Wm3, bm3, (float*)d_out);
}

// round 17
// speedup vs baseline: 3.2125x; 1.0167x over previous
#include <cuda_runtime.h>
#include <cuda_bf16.h>
#include <math.h>
#include <stdint.h>

#define NB   16
#define NN   512
#define DM   256
#define NH   8
#define HDIM 32
#define NL   3
#define NE   4096
#define IND  768
#define FFD  1024
#define ROWS (NB*NN)   // 8192

// ---------------- scratch (device globals; no allocation allowed) ----------
__device__ float g_x   [(size_t)ROWS*DM];
__device__ float g_qkv [(size_t)ROWS*3*DM];
__device__ float g_attn[(size_t)ROWS*DM];
__device__ float g_tmp [(size_t)ROWS*DM];
__device__ float g_ff  [(size_t)ROWS*FFD];
// sparse bias: per-(batch, 8x8 tile grid) edge buckets
__device__ uint2 g_ebuck[(size_t)NB*64*4096];   // 33.5 MB
__device__ int   g_ecnt[NB*64];
// transposed + split weights, [N][K] layout, bf16 hi/lo
#define WT_IN_OFF   0
#define WT_LAYER(l) (196608 + (size_t)(l) * 786432)
#define WT_QKV_OFF  0
#define WT_WO_OFF   196608
#define WT_FF1_OFF  (196608 + 65536)
#define WT_FF2_OFF  (196608 + 65536 + 262144)
__device__ __nv_bfloat16 g_wt_hi[2555904];
__device__ __nv_bfloat16 g_wt_lo[2555904];

// ---------------- helpers --------------------------------------------------
__device__ __forceinline__ uint32_t smem_u32(const void* p) {
    uint32_t a;
    asm("{ .reg .u64 t; cvta.to.shared.u64 t, %1; cvt.u32.u64 %0, t; }" : "=r"(a) : "l"(p));
    return a;
}
__device__ __forceinline__ float geluf(float v) {
    return 0.5f * v * (1.0f + erff(v * 0.7071067811865476f));
}
__device__ __forceinline__ float blockReduceSum(float v, float* sh) {
    int lane = threadIdx.x & 31, w = threadIdx.x >> 5;
    #pragma unroll
    for (int o = 16; o > 0; o >>= 1) v += __shfl_down_sync(0xffffffffu, v, o);
    __syncthreads();
    if (lane == 0) sh[w] = v;
    __syncthreads();
    if (w == 0) {
        int nw = blockDim.x >> 5;
        float t = (lane < nw) ? sh[lane] : 0.0f;
        #pragma unroll
        for (int o = 16; o > 0; o >>= 1) t += __shfl_down_sync(0xffffffffu, t, o);
        if (lane == 0) sh[0] = t;
    }
    __syncthreads();
    return sh[0];
}

#define LDMATRIX_X4(r0, r1, r2, r3, a) \
    asm volatile("ldmatrix.sync.aligned.m8n8.x4.shared.b16 {%0,%1,%2,%3}, [%4];" \
                 : "=r"(r0), "=r"(r1), "=r"(r2), "=r"(r3) : "r"(a))
#define LDMATRIX_X2(r0, r1, a) \
    asm volatile("ldmatrix.sync.aligned.m8n8.x2.shared.b16 {%0,%1}, [%2];" \
                 : "=r"(r0), "=r"(r1) : "r"(a))
#define LDMATRIX_X2_TRANS(r0, r1, a) \
    asm volatile("ldmatrix.sync.aligned.m8n8.x2.trans.shared.b16 {%0,%1}, [%2];" \
                 : "=r"(r0), "=r"(r1) : "r"(a))
#define MMA_BF16(c, a, b) \
    asm volatile("mma.sync.aligned.m16n8k16.row.col.f32.bf16.bf16.f32 " \
                 "{%0,%1,%2,%3}, {%4,%5,%6,%7}, {%8,%9}, {%0,%1,%2,%3};" \
                 : "+f"((c)[0]), "+f"((c)[1]), "+f"((c)[2]), "+f"((c)[3]) \
                 : "r"((a)[0]), "r"((a)[1]), "r"((a)[2]), "r"((a)[3]), \
                   "r"((b)[0]), "r"((b)[1]))

// ---------------- sparse bias build -----------------------------------------
__global__ void ecnt_zero_kernel() {
    int t = blockIdx.x * blockDim.x + threadIdx.x;
    if (t < NB * 64) g_ecnt[t] = 0;
}
__global__ void bucket_kernel(const int* __restrict__ edge_index,
                              const int* __restrict__ edge_type,
                              const float* __restrict__ edge_weight) {
    int t = blockIdx.x * blockDim.x + threadIdx.x;
    if (t >= NB * NE) return;
    int b = t / NE, e = t % NE;
    int src = edge_index[(size_t)b * 2 * NE + e];
    int dst = edge_index[(size_t)b * 2 * NE + NE + e];
    int ty  = edge_type[(size_t)b * NE + e];
    float w = edge_weight[(size_t)b * NE + e];
    int bucket = b * 64 + (src >> 6) * 8 + (dst >> 6);
    int pos = atomicAdd(&g_ecnt[bucket], 1);
    g_ebuck[(size_t)bucket * 4096 + pos] =
        make_uint2(((uint32_t)(src & 63) << 12) | ((uint32_t)(dst & 63) << 4) | (uint32_t)ty,
                   __float_as_uint(w));
}

// --------- weight transpose + bf16 split (batched over layers via grid.z) ---
__global__ void split_kernel(const float* __restrict__ W,
                             __nv_bfloat16* __restrict__ hi, __nv_bfloat16* __restrict__ lo,
                             int K, int Nc, size_t wStride, size_t tStride) {
    __shared__ float t[32][33];
    int layer = blockIdx.z;
    W  += (size_t)layer * wStride;
    hi += (size_t)layer * tStride;
    lo += (size_t)layer * tStride;
    int n0 = blockIdx.x * 32, k0 = blockIdx.y * 32;
    int x = threadIdx.x, y = threadIdx.y;   // 32 x 8
    #pragma unroll
    for (int i = y; i < 32; i += 8) t[i][x] = W[(size_t)(k0 + i) * Nc + n0 + x];
    __syncthreads();
    #pragma unroll
    for (int i = y; i < 32; i += 8) {
        float v = t[x][i];
        __nv_bfloat16 h = __float2bfloat16_rn(v);
        float l = v - __bfloat162float(h);
        size_t o = (size_t)(n0 + i) * K + k0 + x;
        hi[o] = h;
        lo[o] = __float2bfloat16_rn(l);
    }
}

// ---------------- split-bf16 mma.sync GEMM ----------------------------------
// C[M,Nc] = act(A[M,K] @ Wt[Nc,K]^T + bias), fp32-accurate via hi/lo split.
// Block tile 128x128, K-chunk 32, 256 threads (8 warps 4x2), warp tile 32x64.
#define ASTR 40   // bf16 row stride in smem (80B, conflict-free for ldmatrix)
template <int ACT>
__global__ void mma_gemm_kernel(const float* __restrict__ A,
                                const __nv_bfloat16* __restrict__ Whi,
                                const __nv_bfloat16* __restrict__ Wlo,
                                const float* __restrict__ bias, float* __restrict__ C,
                                int K, int Nc) {
    __shared__ __nv_bfloat16 sAh[128 * ASTR], sAl[128 * ASTR];
    __shared__ __nv_bfloat16 sBh[128 * ASTR], sBl[128 * ASTR];
    int tid = threadIdx.x;
    int warp = tid >> 5, lane = tid & 31;
    int wm = warp & 3, wn = warp >> 2;          // warp tile (wm*32, wn*64)
    int bm = blockIdx.y * 128, bn = blockIdx.x * 128;

    float acc[2][8][4];
    #pragma unroll
    for (int i = 0; i < 2; i++)
        #pragma unroll
        for (int j = 0; j < 8; j++)
            #pragma unroll
            for (int q = 0; q < 4; q++) acc[i][j][q] = 0.f;

    int arow = tid >> 1, ahalf = tid & 1;
    const float* ap = A + (size_t)(bm + arow) * K + ahalf * 16;
    const __nv_bfloat16* bph = Whi + (size_t)(bn + arow) * K + ahalf * 16;
    const __nv_bfloat16* bpl = Wlo + (size_t)(bn + arow) * K + ahalf * 16;

    uint32_t uAh = smem_u32(sAh), uAl = smem_u32(sAl);
    uint32_t uBh = smem_u32(sBh), uBl = smem_u32(sBl);

    int a_r = (lane & 7) + ((lane >> 3) & 1) * 8;
    int a_c = (lane >> 4) * 8;
    int ll = lane & 15;
    int b_r = ll & 7;
    int b_c = (ll >> 3) * 8;

    int nchunks = K >> 5;

    float4 aR[4];
    uint4 bRh[2], bRl[2];
    #pragma unroll
    for (int j = 0; j < 4; j++) aR[j] = *(const float4*)(ap + j * 4);
    bRh[0] = *(const uint4*)bph;       bRh[1] = *(const uint4*)(bph + 8);
    bRl[0] = *(const uint4*)bpl;       bRl[1] = *(const uint4*)(bpl + 8);

    for (int c = 0; c < nchunks; c++) {
        #pragma unroll
        for (int j = 0; j < 4; j++) {
            float4 v = aR[j];
            __nv_bfloat162 h0 = __floats2bfloat162_rn(v.x, v.y);
            __nv_bfloat162 h1 = __floats2bfloat162_rn(v.z, v.w);
            __nv_bfloat162 l0 = __floats2bfloat162_rn(v.x - __low2float(h0), v.y - __high2float(h0));
            __nv_bfloat162 l1 = __floats2bfloat162_rn(v.z - __low2float(h1), v.w - __high2float(h1));
            int e = arow * ASTR + ahalf * 16 + j * 4;
            *(__nv_bfloat162*)(sAh + e) = h0; *(__nv_bfloat162*)(sAh + e + 2) = h1;
            *(__nv_bfloat162*)(sAl + e) = l0; *(__nv_bfloat162*)(sAl + e + 2) = l1;
        }
        {
            int e = arow * ASTR + ahalf * 16;
            *(uint4*)(sBh + e) = bRh[0]; *(uint4*)(sBh + e + 8) = bRh[1];
            *(uint4*)(sBl + e) = bRl[0]; *(uint4*)(sBl + e + 8) = bRl[1];
        }
        __syncthreads();

        if (c + 1 < nchunks) {
            int k1 = (c + 1) << 5;
            #pragma unroll
            for (int j = 0; j < 4; j++) aR[j] = *(const float4*)(ap + k1 + j * 4);
            bRh[0] = *(const uint4*)(bph + k1); bRh[1] = *(const uint4*)(bph + k1 + 8);
            bRl[0] = *(const uint4*)(bpl + k1); bRl[1] = *(const uint4*)(bpl + k1 + 8);
        }

        #pragma unroll
        for (int s = 0; s < 32; s += 16) {
            uint32_t ah[2][4], al[2][4];
            #pragma unroll
            for (int mi = 0; mi < 2; mi++) {
                int off = ((wm * 32 + mi * 16 + a_r) * ASTR + s + a_c) * 2;
                LDMATRIX_X4(ah[mi][0], ah[mi][1], ah[mi][2], ah[mi][3], uAh + off);
                LDMATRIX_X4(al[mi][0], al[mi][1], al[mi][2], al[mi][3], uAl + off);
            }
            #pragma unroll
            for (int ni = 0; ni < 8; ni++) {
                uint32_t bh[2], bl[2];
                int off = ((wn * 64 + ni * 8 + b_r) * ASTR + s + b_c) * 2;
                LDMATRIX_X2(bh[0], bh[1], uBh + off);
                LDMATRIX_X2(bl[0], bl[1], uBl + off);
                #pragma unroll
                for (int mi = 0; mi < 2; mi++) {
                    MMA_BF16(acc[mi][ni], ah[mi], bh);
                    MMA_BF16(acc[mi][ni], ah[mi], bl);
                    MMA_BF16(acc[mi][ni], al[mi], bh);
                }
            }
        }
        __syncthreads();
    }

    int gid = lane >> 2, tid2 = (lane & 3) * 2;
    #pragma unroll
    for (int mi = 0; mi < 2; mi++) {
        #pragma unroll
        for (int ni = 0; ni < 8; ni++) {
            int row = bm + wm * 32 + mi * 16 + gid;
            int col = bn + wn * 64 + ni * 8 + tid2;
            float b0 = bias[col], b1 = bias[col + 1];
            float v0 = acc[mi][ni][0] + b0, v1 = acc[mi][ni][1] + b1;
            float v2 = acc[mi][ni][2] + b0, v3 = acc[mi][ni][3] + b1;
            if (ACT == 1) { v0 = geluf(v0); v1 = geluf(v1); v2 = geluf(v2); v3 = geluf(v3); }
            *(float2*)&C[(size_t)row * Nc + col] = make_float2(v0, v1);
            *(float2*)&C[(size_t)(row + 8) * Nc + col] = make_float2(v2, v3);
        }
    }
}

// ---------------- attention (flash-style, tensor-core, sparse bias) ---------
// Block = (b,h, 64-row q-tile). 128 threads, 4 warps, warp = 16 q-rows.
// Bias built per 64x64 tile in smem from edge buckets (no dense bias tensor).
__global__ void attn_mma_kernel(const float* __restrict__ qkv,
                                const float* __restrict__ et_emb,
                                const int* __restrict__ node_mask,
                                float* __restrict__ outp) {
    __shared__ __nv_bfloat16 sQh[64 * ASTR], sQl[64 * ASTR];
    __shared__ __nv_bfloat16 sKh[64 * ASTR], sKl[64 * ASTR];
    __shared__ __nv_bfloat16 sV [64 * ASTR];
    __shared__ float maskb[64];
    __shared__ float sB[64][66];
    __shared__ float sE[32];

    int bh = blockIdx.y, b = bh >> 3, h = bh & 7;
    int i0 = blockIdx.x * 64;
    int tid = threadIdx.x, warp = tid >> 5, lane = tid & 31;
    int gid = lane >> 2, qd = lane & 3, ll = lane & 15;
    const float scale = 0.17677669529663687f;   // 1/sqrt(32)

    if (tid < 32) sE[tid] = et_emb[tid];

    // load Q (64 x 32) with hi/lo split
    {
        int row = tid >> 1, halfq = tid & 1;
        const float* qp = qkv + ((size_t)(b * NN + i0 + row)) * (3 * DM) + h * HDIM + halfq * 16;
        #pragma unroll
        for (int j = 0; j < 4; j++) {
            float4 v = *(const float4*)(qp + j * 4);
            __nv_bfloat162 h0 = __floats2bfloat162_rn(v.x, v.y);
            __nv_bfloat162 h1 = __floats2bfloat162_rn(v.z, v.w);
            __nv_bfloat162 l0 = __floats2bfloat162_rn(v.x - __low2float(h0), v.y - __high2float(h0));
            __nv_bfloat162 l1 = __floats2bfloat162_rn(v.z - __low2float(h1), v.w - __high2float(h1));
            int e = row * ASTR + halfq * 16 + j * 4;
            *(__nv_bfloat162*)(sQh + e) = h0; *(__nv_bfloat162*)(sQh + e + 2) = h1;
            *(__nv_bfloat162*)(sQl + e) = l0; *(__nv_bfloat162*)(sQl + e + 2) = l1;
        }
    }

    float m0 = -INFINITY, m1 = -INFINITY, l0 = 0.f, l1 = 0.f;
    float oc[4][4];
    #pragma unroll
    for (int i = 0; i < 4; i++)
        #pragma unroll
        for (int j = 0; j < 4; j++) oc[i][j] = 0.f;

    int a_r = (lane & 7) + ((lane >> 3) & 1) * 8;
    int a_c = (lane >> 4) * 8;
    int b_r = ll & 7, b_c = (ll >> 3) * 8;

    uint32_t uQh = smem_u32(sQh), uQl = smem_u32(sQl);
    uint32_t uKh = smem_u32(sKh), uKl = smem_u32(sKl), uV = smem_u32(sV);

    int grow = i0 + warp * 16 + gid;
    int r0l = warp * 16 + gid;          // local q row of fragment rows 0/1

    for (int j0 = 0; j0 < NN; j0 += 64) {
        __syncthreads();
        // load K (split) + V (plain) chunk; zero bias tile
        {
            int row = tid >> 1, halfq = tid & 1;
            const float* kp = qkv + ((size_t)(b * NN + j0 + row)) * (3 * DM) + DM + h * HDIM + halfq * 16;
            const float* vp = kp + DM;
            #pragma unroll
            for (int j = 0; j < 4; j++) {
                float4 v = *(const float4*)(kp + j * 4);
                __nv_bfloat162 h0 = __floats2bfloat162_rn(v.x, v.y);
                __nv_bfloat162 h1 = __floats2bfloat162_rn(v.z, v.w);
                __nv_bfloat162 l0 = __floats2bfloat162_rn(v.x - __low2float(h0), v.y - __high2float(h0));
                __nv_bfloat162 l1 = __floats2bfloat162_rn(v.z - __low2float(h1), v.w - __high2float(h1));
                int e = row * ASTR + halfq * 16 + j * 4;
                *(__nv_bfloat162*)(sKh + e) = h0; *(__nv_bfloat162*)(sKh + e + 2) = h1;
                *(__nv_bfloat162*)(sKl + e) = l0; *(__nv_bfloat162*)(sKl + e + 2) = l1;
                float4 vv = *(const float4*)(vp + j * 4);
                *(__nv_bfloat162*)(sV + e)     = __floats2bfloat162_rn(vv.x, vv.y);
                *(__nv_bfloat162*)(sV + e + 2) = __floats2bfloat162_rn(vv.z, vv.w);
            }
        }
        if (tid < 64) maskb[tid] = node_mask[b * NN + j0 + tid] ? 0.f : -INFINITY;
        for (int idx = tid; idx < 64 * 66; idx += 128) ((float*)sB)[idx] = 0.f;
        __syncthreads();

        // scatter this tile's edges into smem bias
        {
            int bucket = b * 64 + (i0 >> 6) * 8 + (j0 >> 6);
            int cnt = g_ecnt[bucket];
            const uint2* eb = g_ebuck + (size_t)bucket * 4096;
            for (int e = tid; e < cnt; e += 128) {
                uint2 pk = eb[e];
                int row = (pk.x >> 12) & 63, col = (pk.x >> 4) & 63, ty = pk.x & 15;
                float val = sE[ty * 8 + h] + (ty == 2 ? __uint_as_float(pk.y) : 0.f);
                atomicAdd(&sB[row][col], val);
            }
        }

        // Q fragments (2 k-steps)
        uint32_t qh[2][4], ql[2][4];
        #pragma unroll
        for (int s = 0; s < 2; s++) {
            int off = ((warp * 16 + a_r) * ASTR + s * 16 + a_c) * 2;
            LDMATRIX_X4(qh[s][0], qh[s][1], qh[s][2], qh[s][3], uQh + off);
            LDMATRIX_X4(ql[s][0], ql[s][1], ql[s][2], ql[s][3], uQl + off);
        }
        // S = QK^T (split, 3 MMAs per k-step)
        float sc[8][4];
        #pragma unroll
        for (int ni = 0; ni < 8; ni++) {
            sc[ni][0] = sc[ni][1] = sc[ni][2] = sc[ni][3] = 0.f;
            #pragma unroll
            for (int s = 0; s < 2; s++) {
                uint32_t kh[2], kl[2];
                int off = ((ni * 8 + b_r) * ASTR + s * 16 + b_c) * 2;
                LDMATRIX_X2(kh[0], kh[1], uKh + off);
                LDMATRIX_X2(kl[0], kl[1], uKl + off);
                MMA_BF16(sc[ni], qh[s], kh);
                MMA_BF16(sc[ni], qh[s], kl);
                MMA_BF16(sc[ni], ql[s], kh);
            }
        }
        __syncthreads();   // bias scatter complete before sB reads

        // scale + bias + mask, row maxes
        float mx0 = -INFINITY, mx1 = -INFINITY;
        #pragma unroll
        for (int ni = 0; ni < 8; ni++) {
            int col = ni * 8 + qd * 2;
            float2 bv0 = *(const float2*)&sB[r0l][col];
            float2 bv1 = *(const float2*)&sB[r0l + 8][col];
            sc[ni][0] = sc[ni][0] * scale + bv0.x + maskb[col];
            sc[ni][1] = sc[ni][1] * scale + bv0.y + maskb[col + 1];
            sc[ni][2] = sc[ni][2] * scale + bv1.x + maskb[col];
            sc[ni][3] = sc[ni][3] * scale + bv1.y + maskb[col + 1];
            mx0 = fmaxf(mx0, fmaxf(sc[ni][0], sc[ni][1]));
            mx1 = fmaxf(mx1, fmaxf(sc[ni][2], sc[ni][3]));
        }
        mx0 = fmaxf(mx0, __shfl_xor_sync(0xffffffffu, mx0, 1));
        mx0 = fmaxf(mx0, __shfl_xor_sync(0xffffffffu, mx0, 2));
        mx1 = fmaxf(mx1, __shfl_xor_sync(0xffffffffu, mx1, 1));
        mx1 = fmaxf(mx1, __shfl_xor_sync(0xffffffffu, mx1, 2));

        float mn0 = fmaxf(m0, mx0), mn1 = fmaxf(m1, mx1);
        float c0 = (mn0 == -INFINITY) ? 1.f : __expf(m0 - mn0);
        float c1 = (mn1 == -INFINITY) ? 1.f : __expf(m1 - mn1);
        float ls0 = 0.f, ls1 = 0.f;
        #pragma unroll
        for (int ni = 0; ni < 8; ni++) {
            float p0 = (sc[ni][0] == -INFINITY) ? 0.f : __expf(sc[ni][0] - mn0);
            float p1 = (sc[ni][1] == -INFINITY) ? 0.f : __expf(sc[ni][1] - mn0);
            float p2 = (sc[ni][2] == -INFINITY) ? 0.f : __expf(sc[ni][2] - mn1);
            float p3 = (sc[ni][3] == -INFINITY) ? 0.f : __expf(sc[ni][3] - mn1);
            sc[ni][0] = p0; sc[ni][1] = p1; sc[ni][2] = p2; sc[ni][3] = p3;
            ls0 += p0 + p1; ls1 += p2 + p3;
        }
        ls0 += __shfl_xor_sync(0xffffffffu, ls0, 1);
        ls0 += __shfl_xor_sync(0xffffffffu, ls0, 2);
        ls1 += __shfl_xor_sync(0xffffffffu, ls1, 1);
        ls1 += __shfl_xor_sync(0xffffffffu, ls1, 2);
        l0 = l0 * c0 + ls0;
        l1 = l1 * c1 + ls1;
        #pragma unroll
        for (int ni = 0; ni < 4; ni++) {
            oc[ni][0] *= c0; oc[ni][1] *= c0;
            oc[ni][2] *= c1; oc[ni][3] *= c1;
        }
        m0 = mn0; m1 = mn1;

        // P·V: C-fragments of S pack directly into A-fragments
        #pragma unroll
        for (int ks = 0; ks < 4; ks++) {
            uint32_t pa[4];
            __nv_bfloat162 t0 = __floats2bfloat162_rn(sc[2*ks][0], sc[2*ks][1]);
            __nv_bfloat162 t1 = __floats2bfloat162_rn(sc[2*ks][2], sc[2*ks][3]);
            __nv_bfloat162 t2 = __floats2bfloat162_rn(sc[2*ks+1][0], sc[2*ks+1][1]);
            __nv_bfloat162 t3 = __floats2bfloat162_rn(sc[2*ks+1][2], sc[2*ks+1][3]);
            pa[0] = *(uint32_t*)&t0; pa[1] = *(uint32_t*)&t1;
            pa[2] = *(uint32_t*)&t2; pa[3] = *(uint32_t*)&t3;
            #pragma unroll
            for (int ni = 0; ni < 4; ni++) {
                uint32_t vb[2];
                int off = ((ks * 16 + ll) * ASTR + ni * 8) * 2;
                LDMATRIX_X2_TRANS(vb[0], vb[1], uV + off);
                MMA_BF16(oc[ni], pa, vb);
            }
        }
    }

    float inv0 = (l0 > 0.f) ? 1.f / l0 : 0.f;
    float inv1 = (l1 > 0.f) ? 1.f / l1 : 0.f;
    float* op0 = outp + ((size_t)(b * NN + grow)) * DM + h * HDIM;
    float* op1 = op0 + 8 * DM;
    #pragma unroll
    for (int ni = 0; ni < 4; ni++) {
        int col = ni * 8 + qd * 2;
        *(float2*)(op0 + col) = make_float2(oc[ni][0] * inv0, oc[ni][1] * inv0);
        *(float2*)(op1 + col) = make_float2(oc[ni][2] * inv1, oc[ni][3] * inv1);
    }
}

// ---------------- residual + LayerNorm (warp per row, shuffle-only) ---------
__global__ void add_ln_kernel(const float* __restrict__ xin, const float* __restrict__ res,
                              const float* __restrict__ g, const float* __restrict__ bb,
                              float* __restrict__ xout) {
    int warp = threadIdx.x >> 5, lane = threadIdx.x & 31;
    int row = blockIdx.x * 8 + warp;
    const float4* xp = (const float4*)(xin + (size_t)row * DM);
    const float4* rp = (const float4*)(res + (size_t)row * DM);
    float4 a0 = xp[lane * 2], a1 = xp[lane * 2 + 1];
    float4 r0 = rp[lane * 2], r1 = rp[lane * 2 + 1];
    float v[8] = {a0.x + r0.x, a0.y + r0.y, a0.z + r0.z, a0.w + r0.w,
                  a1.x + r1.x, a1.y + r1.y, a1.z + r1.z, a1.w + r1.w};
    float s = 0.f;
    #pragma unroll
    for (int i = 0; i < 8; i++) s += v[i];
    #pragma unroll
    for (int o = 16; o > 0; o >>= 1) s += __shfl_xor_sync(0xffffffffu, s, o);
    float mu = s * (1.0f / DM);
    float q = 0.f;
    #pragma unroll
    for (int i = 0; i < 8; i++) { v[i] -= mu; q += v[i] * v[i]; }
    #pragma unroll
    for (int o = 16; o > 0; o >>= 1) q += __shfl_xor_sync(0xffffffffu, q, o);
    float rstd = rsqrtf(q * (1.0f / DM) + 1e-5f);
    const float4* gp = (const float4*)g;
    const float4* bp = (const float4*)bb;
    float4 g0 = gp[lane * 2], g1 = gp[lane * 2 + 1];
    float4 b0 = bp[lane * 2], b1 = bp[lane * 2 + 1];
    float4 o0, o1;
    o0.x = v[0] * rstd * g0.x + b0.x; o0.y = v[1] * rstd * g0.y + b0.y;
    o0.z = v[2] * rstd * g0.z + b0.z; o0.w = v[3] * rstd * g0.w + b0.w;
    o1.x = v[4] * rstd * g1.x + b1.x; o1.y = v[5] * rstd * g1.y + b1.y;
    o1.z = v[6] * rstd * g1.z + b1.z; o1.w = v[7] * rstd * g1.w + b1.w;
    float4* op = (float4*)(xout + (size_t)row * DM);
    op[lane * 2] = o0; op[lane * 2 + 1] = o1;
}

// ---------------- pooling + MLP head ---------------------------------------
__global__ void head_kernel(const float* __restrict__ x,
                            const int* __restrict__ tmask, const int* __restrict__ imask,
                            const int* __restrict__ gidx,
                            const float* __restrict__ Wm1, const float* __restrict__ bm1,
                            const float* __restrict__ Wm2, const float* __restrict__ bm2,
                            const float* __restrict__ Wm3, const float* __restrict__ bm3,
                            float* __restrict__ out) {
    __shared__ float red[32];
    __shared__ float comb[769];
    __shared__ float h1[512];
    __shared__ float h2[256];
    int b = blockIdx.x, tid = threadIdx.x;

    float tcp = 0.f, icp = 0.f;
    for (int n = tid; n < NN; n += 256) {
        tcp += (tmask[b * NN + n] != 0) ? 1.f : 0.f;
        icp += (imask[b * NN + n] != 0) ? 1.f : 0.f;
    }
    float tc = fmaxf(blockReduceSum(tcp, red), 1.f);
    float ic = fmaxf(blockReduceSum(icp, red), 1.f);

    int d = tid;
    float tp = 0.f, ip = 0.f;
    for (int n = 0; n < NN; n++) {
        float v = x[((size_t)(b * NN + n)) * DM + d];
        if (tmask[b * NN + n] != 0) tp += v;
        if (imask[b * NN + n] != 0) ip += v;
    }
    tp /= tc; ip /= ic;
    int gi = gidx[b];
    float ge = x[((size_t)(b * NN + gi)) * DM + d];

    float n1s = blockReduceSum(tp * tp, red);
    float n2s = blockReduceSum(ip * ip, red);
    float dt  = blockReduceSum(tp * ip, red);
    float n1 = fmaxf(sqrtf(n1s), 1e-6f), n2 = fmaxf(sqrtf(n2s), 1e-6f);
    float conflict = 1.f - dt / (n1 * n2);

    comb[d] = ge; comb[256 + d] = tp; comb[512 + d] = ip;
    if (tid == 0) comb[768] = conflict;
    __syncthreads();

    for (int j = tid; j < 512; j += 256) {
        float a = bm1[j];
        for (int i = 0; i < 769; i++) a += comb[i] * Wm1[(size_t)i * 512 + j];
        h1[j] = geluf(a);
    }
    __syncthreads();
    {
        float a = bm2[tid];
        for (int i = 0; i < 512; i++) a += h1[i] * Wm2[(size_t)i * 256 + tid];
        h2[tid] = geluf(a);
    }
    __syncthreads();
    float tot = blockReduceSum(h2[tid] * Wm3[tid], red);
    if (tid == 0) out[b] = tot + bm3[0];
}

// ---------------- launch ----------------------------------------------------
extern "C" void kernel_launch(void* const* d_in, const int* in_sizes, int n_in,
                              void* d_out, int out_size) {
    const float* node_feats = (const float*)d_in[0];
    const int*   node_mask  = (const int*)d_in[1];
    const int*   text_mask  = (const int*)d_in[2];
    const int*   image_mask = (const int*)d_in[3];
    const int*   gidx       = (const int*)d_in[4];
    const int*   edge_index = (const int*)d_in[5];
    const int*   edge_type  = (const int*)d_in[6];
    const float* edge_weight= (const float*)d_in[7];
    const float* W_in  = (const float*)d_in[8];
    const float* b_in  = (const float*)d_in[9];
    const float* Wqkv  = (const float*)d_in[10];
    const float* bqkv  = (const float*)d_in[11];
    const float* Wo    = (const float*)d_in[12];
    const float* bo    = (const float*)d_in[13];
    const float* ln1_g = (const float*)d_in[14];
    const float* ln1_b = (const float*)d_in[15];
    const float* ln2_g = (const float*)d_in[16];
    const float* ln2_b = (const float*)d_in[17];
    const float* Wff1  = (const float*)d_in[18];
    const float* bff1  = (const float*)d_in[19];
    const float* Wff2  = (const float*)d_in[20];
    const float* bff2  = (const float*)d_in[21];
    const float* et_emb= (const float*)d_in[22];
    const float* Wm1   = (const float*)d_in[23];
    const float* bm1   = (const float*)d_in[24];
    const float* Wm2   = (const float*)d_in[25];
    const float* bm2   = (const float*)d_in[26];
    const float* Wm3   = (const float*)d_in[27];
    const float* bm3   = (const float*)d_in[28];

    float *x, *qkv, *attn, *tmp, *ff;
    __nv_bfloat16 *wth, *wtl;
    cudaGetSymbolAddress((void**)&x,    g_x);
    cudaGetSymbolAddress((void**)&qkv,  g_qkv);
    cudaGetSymbolAddress((void**)&attn, g_attn);
    cudaGetSymbolAddress((void**)&tmp,  g_tmp);
    cudaGetSymbolAddress((void**)&ff,   g_ff);
    cudaGetSymbolAddress((void**)&wth,  g_wt_hi);
    cudaGetSymbolAddress((void**)&wtl,  g_wt_lo);

    // ---- sparse bias buckets ----
    ecnt_zero_kernel<<<4, 256>>>();
    bucket_kernel<<<(NB * NE + 255) / 256, 256>>>(edge_index, edge_type, edge_weight);

    // ---- weight transpose + split (W[K,N] -> hi/lo[N,K]); layers batched ----
    split_kernel<<<dim3(DM / 32, IND / 32, 1), dim3(32, 8)>>>(
        W_in, wth + WT_IN_OFF, wtl + WT_IN_OFF, IND, DM, 0, 0);
    split_kernel<<<dim3(3 * DM / 32, DM / 32, NL), dim3(32, 8)>>>(
        Wqkv, wth + WT_LAYER(0) + WT_QKV_OFF, wtl + WT_LAYER(0) + WT_QKV_OFF,
        DM, 3 * DM, (size_t)DM * 3 * DM, 786432);
    split_kernel<<<dim3(DM / 32, DM / 32, NL), dim3(32, 8)>>>(
        Wo, wth + WT_LAYER(0) + WT_WO_OFF, wtl + WT_LAYER(0) + WT_WO_OFF,
        DM, DM, (size_t)DM * DM, 786432);
    split_kernel<<<dim3(FFD / 32, DM / 32, NL), dim3(32, 8)>>>(
        Wff1, wth + WT_LAYER(0) + WT_FF1_OFF, wtl + WT_LAYER(0) + WT_FF1_OFF,
        DM, FFD, (size_t)DM * FFD, 786432);
    split_kernel<<<dim3(DM / 32, FFD / 32, NL), dim3(32, 8)>>>(
        Wff2, wth + WT_LAYER(0) + WT_FF2_OFF, wtl + WT_LAYER(0) + WT_FF2_OFF,
        FFD, DM, (size_t)FFD * DM, 786432);

    // input projection
    mma_gemm_kernel<0><<<dim3(DM / 128, ROWS / 128), 256>>>(
        node_feats, wth + WT_IN_OFF, wtl + WT_IN_OFF, b_in, x, IND, DM);

    for (int l = 0; l < NL; l++) {
        size_t lo = WT_LAYER(l);
        mma_gemm_kernel<0><<<dim3(3 * DM / 128, ROWS / 128), 256>>>(
            x, wth + lo + WT_QKV_OFF, wtl + lo + WT_QKV_OFF, bqkv + (size_t)l * 3 * DM, qkv, DM, 3 * DM);
        attn_mma_kernel<<<dim3(NN / 64, NB * NH), 128>>>(qkv, et_emb, node_mask, attn);
        mma_gemm_kernel<0><<<dim3(DM / 128, ROWS / 128), 256>>>(
            attn, wth + lo + WT_WO_OFF, wtl + lo + WT_WO_OFF, bo + (size_t)l * DM, tmp, DM, DM);
        add_ln_kernel<<<ROWS / 8, 256>>>(x, tmp, ln1_g + (size_t)l * DM, ln1_b + (size_t)l * DM, x);
        mma_gemm_kernel<1><<<dim3(FFD / 128, ROWS / 128), 256>>>(
            x, wth + lo + WT_FF1_OFF, wtl + lo + WT_FF1_OFF, bff1 + (size_t)l * FFD, ff, DM, FFD);
        mma_gemm_kernel<0><<<dim3(DM / 128, ROWS / 128), 256>>>(
            ff, wth + lo + WT_FF2_OFF, wtl + lo + WT_FF2_OFF, bff2 + (size_t)l * DM, tmp, FFD, DM);
        add_ln_kernel<<<ROWS / 8, 256>>>(x, tmp, ln2_g + (size_t)l * DM, ln2_b + (size_t)l * DM, x);
    }

    head_kernel<<<NB, 256>>>(x, text_mask, image_mask, gidx,
                             Wm1, bm1, Wm2, bm2, Wm3, bm3, (float*)d_out);
}